// round 2
// baseline (speedup 1.0000x reference)
#include <cuda_runtime.h>
#include <cstdint>
#include <cstddef>

#define VOCAB 32000
#define EMB   256
#define HID   512
#define FEAT  1024
#define BATCH 32
#define TT    100
#define M_ROWS (TT*BATCH)      // 3200
#define NBLK_LSTM 128

// ---------------------------------------------------------------------------
// device scratch (static allocations only — no cudaMalloc allowed)
// ---------------------------------------------------------------------------
__device__ float g_pooled[BATCH*FEAT];                    // 128 KB
__device__ float g_xg[(size_t)M_ROWS * 4 * HID];          // 26.2 MB: x@W_ih^T + b_ih + b_hh
__device__ float g_hall[(size_t)M_ROWS * HID];            // 6.55 MB: h_t for all (t,b)
__device__ float g_hping[2][BATCH*HID];                   // ping-pong h across steps
__device__ int   g_tok[M_ROWS];                           // teacher-forced tokens
__device__ unsigned g_barrier;                            // grid barrier counter

// ---------------------------------------------------------------------------
// packed fp32x2 FMA (sm_100+)
// ---------------------------------------------------------------------------
__device__ __forceinline__ unsigned long long pack2(float x, float y) {
    unsigned long long r;
    asm("mov.b64 %0, {%1, %2};" : "=l"(r) : "r"(__float_as_uint(x)), "r"(__float_as_uint(y)));
    return r;
}
__device__ __forceinline__ void ffma2(unsigned long long& d, unsigned long long a, unsigned long long b) {
    asm("fma.rn.f32x2 %0, %1, %2, %3;" : "=l"(d) : "l"(a), "l"(b), "l"(d));
}

// ---------------------------------------------------------------------------
// prep: tokens + barrier reset
// tok[m], m = t*32+b : t==0 ? START(1) : reports[b][t-1]
// ---------------------------------------------------------------------------
__global__ void prep_kernel(const int* __restrict__ reports) {
    int i = blockIdx.x * blockDim.x + threadIdx.x;
    if (i == 0) g_barrier = 0u;
    if (i < M_ROWS) {
        int t = i >> 5, b = i & 31;
        g_tok[i] = (t == 0) ? 1 : reports[b * TT + (t - 1)];
    }
}

// ---------------------------------------------------------------------------
// pooled[b][f] = mean over 7x7
// ---------------------------------------------------------------------------
__global__ void pool_kernel(const float* __restrict__ feat) {
    int i = blockIdx.x * blockDim.x + threadIdx.x;
    if (i < BATCH * FEAT) {
        const float* p = feat + (size_t)i * 49;
        float s = 0.f;
        #pragma unroll
        for (int j = 0; j < 49; j++) s += p[j];
        g_pooled[i] = s * (1.f / 49.f);
    }
}

// ---------------------------------------------------------------------------
// h0[b][j] = pooled[b] . fc_w[j] + fc_b[j]  -> g_hping[0]
// ---------------------------------------------------------------------------
__global__ void h0_kernel(const float* __restrict__ fc_w, const float* __restrict__ fc_b) {
    int i = blockIdx.x * blockDim.x + threadIdx.x;   // 16384 threads
    if (i >= BATCH * HID) return;
    int b = i >> 9, j = i & 511;
    const float* pw = fc_w + (size_t)j * FEAT;
    const float* pp = g_pooled + (size_t)b * FEAT;
    float acc = fc_b[j];
    #pragma unroll 4
    for (int k = 0; k < FEAT; k++) acc = fmaf(pw[k], pp[k], acc);
    g_hping[0][b * HID + j] = acc;
}

// ---------------------------------------------------------------------------
// generic fp32 SIMT GEMM:  C[M,N] = Arow(m) . B[n] (+bias0[n] (+bias1[n]))
// A rows K-major (optionally gathered from emb table), B rows K-major.
// BM=BN=128, BK=16, 256 threads, 8x8 thread tile, f32x2 packed FMA.
// M is always 3200 here; M,N,K multiples of 128/128/16 (no predicates).
// PERMOUT: row m=(t*32+b) written to C[b*TT*N + t*N + n].
// ---------------------------------------------------------------------------
template<bool GATHER, bool PERMOUT>
__global__ __launch_bounds__(256)
void gemm_kernel(const float* __restrict__ Asrc, const float* __restrict__ Bsrc,
                 const float* __restrict__ bias0, const float* __restrict__ bias1,
                 float* __restrict__ C, int N, int K, const int* __restrict__ gidx)
{
    __shared__ float As[16 * 132];
    __shared__ float Bs[16 * 132];
    const int tid = threadIdx.x;
    const int n0 = blockIdx.x * 128;
    const int m0 = blockIdx.y * 128;
    const int ty = tid >> 4;          // 0..15  (M dir)
    const int tx = tid & 15;          // 0..15  (N dir)

    unsigned long long acc[8][4];
    #pragma unroll
    for (int i = 0; i < 8; i++)
        #pragma unroll
        for (int j = 0; j < 4; j++) acc[i][j] = 0ull;

    // loader mapping: thread loads 2 rows (ml, ml+64) x 4 consecutive k (kq)
    const int ml = tid >> 2;
    const int kq = (tid & 3) * 4;
    const float* arow0;
    const float* arow1;
    if (GATHER) {
        arow0 = Asrc + (size_t)gidx[m0 + ml] * K;
        arow1 = Asrc + (size_t)gidx[m0 + ml + 64] * K;
    } else {
        arow0 = Asrc + (size_t)(m0 + ml) * K;
        arow1 = Asrc + (size_t)(m0 + ml + 64) * K;
    }
    const float* brow0 = Bsrc + (size_t)(n0 + ml) * K;
    const float* brow1 = Bsrc + (size_t)(n0 + ml + 64) * K;

    for (int k0 = 0; k0 < K; k0 += 16) {
        float4 a0  = *reinterpret_cast<const float4*>(arow0 + k0 + kq);
        float4 a1  = *reinterpret_cast<const float4*>(arow1 + k0 + kq);
        float4 bb0 = *reinterpret_cast<const float4*>(brow0 + k0 + kq);
        float4 bb1 = *reinterpret_cast<const float4*>(brow1 + k0 + kq);
        __syncthreads();
        As[(kq+0)*132 + ml] = a0.x;  As[(kq+1)*132 + ml] = a0.y;
        As[(kq+2)*132 + ml] = a0.z;  As[(kq+3)*132 + ml] = a0.w;
        As[(kq+0)*132 + ml+64] = a1.x;  As[(kq+1)*132 + ml+64] = a1.y;
        As[(kq+2)*132 + ml+64] = a1.z;  As[(kq+3)*132 + ml+64] = a1.w;
        Bs[(kq+0)*132 + ml] = bb0.x; Bs[(kq+1)*132 + ml] = bb0.y;
        Bs[(kq+2)*132 + ml] = bb0.z; Bs[(kq+3)*132 + ml] = bb0.w;
        Bs[(kq+0)*132 + ml+64] = bb1.x; Bs[(kq+1)*132 + ml+64] = bb1.y;
        Bs[(kq+2)*132 + ml+64] = bb1.z; Bs[(kq+3)*132 + ml+64] = bb1.w;
        __syncthreads();

        #pragma unroll
        for (int kk = 0; kk < 16; kk++) {
            const float* ar = As + kk*132 + ty*8;
            const float* br = Bs + kk*132 + tx*8;
            float4 av0 = *reinterpret_cast<const float4*>(ar);
            float4 av1 = *reinterpret_cast<const float4*>(ar + 4);
            float4 bv0 = *reinterpret_cast<const float4*>(br);
            float4 bv1 = *reinterpret_cast<const float4*>(br + 4);
            unsigned long long bp0 = pack2(bv0.x, bv0.y);
            unsigned long long bp1 = pack2(bv0.z, bv0.w);
            unsigned long long bp2 = pack2(bv1.x, bv1.y);
            unsigned long long bp3 = pack2(bv1.z, bv1.w);
            float aa[8] = {av0.x, av0.y, av0.z, av0.w, av1.x, av1.y, av1.z, av1.w};
            #pragma unroll
            for (int i = 0; i < 8; i++) {
                unsigned long long ap = pack2(aa[i], aa[i]);
                ffma2(acc[i][0], ap, bp0);
                ffma2(acc[i][1], ap, bp1);
                ffma2(acc[i][2], ap, bp2);
                ffma2(acc[i][3], ap, bp3);
            }
        }
    }

    // epilogue
    float bias[8];
    #pragma unroll
    for (int j = 0; j < 8; j++) {
        int n = n0 + tx*8 + j;
        float bv = bias0 ? bias0[n] : 0.f;
        if (bias1) bv += bias1[n];
        bias[j] = bv;
    }
    #pragma unroll
    for (int i = 0; i < 8; i++) {
        int m = m0 + ty*8 + i;
        size_t base;
        if (PERMOUT) {
            base = ((size_t)(m & 31) * TT + (size_t)(m >> 5)) * (size_t)N + (size_t)(n0 + tx*8);
        } else {
            base = (size_t)m * (size_t)N + (size_t)(n0 + tx*8);
        }
        float o[8];
        #pragma unroll
        for (int j = 0; j < 4; j++) {
            o[2*j]   = __uint_as_float((unsigned)(acc[i][j]))       + bias[2*j];
            o[2*j+1] = __uint_as_float((unsigned)(acc[i][j] >> 32)) + bias[2*j+1];
        }
        *reinterpret_cast<float4*>(C + base)     = make_float4(o[0], o[1], o[2], o[3]);
        *reinterpret_cast<float4*>(C + base + 4) = make_float4(o[4], o[5], o[6], o[7]);
    }
}

// ---------------------------------------------------------------------------
// grid barrier (non-cooperative; all 128 blocks guaranteed resident on 148 SMs)
// ---------------------------------------------------------------------------
__device__ __forceinline__ void grid_barrier(unsigned target) {
    __syncthreads();
    __threadfence();
    if (threadIdx.x == 0) {
        atomicAdd(&g_barrier, 1u);
        while (*((volatile unsigned*)&g_barrier) < target) { __nanosleep(64); }
    }
    __syncthreads();
    __threadfence();
}

// ---------------------------------------------------------------------------
// persistent LSTM recurrence.
// 128 blocks x 128 threads. Block bid owns hidden units n0..n0+3 → 16 gate
// rows (lr = u*4+g → global row g*512+n0+u), W_hh slice cached in SMEM once.
// Per step: load h (ping) → SMEM, 512 dots of len 512 (2 rows x 2 batches per
// thread), add xg, gate nonlinearities, write h (pong + hall), grid barrier.
// smem: ws 16*512 | hs 32*513 (conflict-free scalar) | gsm 16*33  = 100544 B
// ---------------------------------------------------------------------------
__global__ __launch_bounds__(128)
void lstm_kernel(const float* __restrict__ Whh) {
    extern __shared__ float sm[];
    float* ws  = sm;                       // 16*512
    float* hs  = sm + 16*512;              // 32*513
    float* gsm = sm + 16*512 + 32*513;     // 16*33

    const int tid = threadIdx.x;
    const int n0  = blockIdx.x * 4;

    // cache W_hh slice (row order lr = u*4+g)
    for (int lr = 0; lr < 16; lr++) {
        int u = lr >> 2, g = lr & 3;
        const float* src = Whh + (size_t)(g * HID + n0 + u) * HID;
        for (int k = tid; k < HID; k += 128) ws[lr * HID + k] = src[k];
    }

    const int rp = tid >> 4;            // 0..7
    const int r0 = rp * 2, r1 = r0 + 1; // local gate rows
    const int bp = tid & 15;
    const int b0 = bp * 2, b1 = b0 + 1; // batches
    const int cu = tid >> 5;            // phase-C unit 0..3
    const int cb = tid & 31;            // phase-C batch
    float c_reg = 0.f;

    __syncthreads();

    for (int t = 0; t < TT; t++) {
        // phase A: h(ping) -> hs[b*513+k]  (L2 reads: other SMs wrote it)
        const float* hin = g_hping[t & 1];
        for (int i = tid; i < BATCH * (HID/4); i += 128) {
            int b  = i >> 7;            // 512/4=128 vec4 per row
            int kk = (i & 127) * 4;
            float4 v = __ldcg(reinterpret_cast<const float4*>(hin + b * HID + kk));
            float* d = hs + b * 513 + kk;
            d[0] = v.x; d[1] = v.y; d[2] = v.z; d[3] = v.w;
        }
        __syncthreads();

        // phase B: 2 rows x 2 batches per thread
        const float* w0 = ws + r0 * HID;
        const float* w1 = ws + r1 * HID;
        const float* ha = hs + b0 * 513;
        const float* hb = hs + b1 * 513;
        float a00 = 0.f, a01 = 0.f, a10 = 0.f, a11 = 0.f;
        #pragma unroll 8
        for (int k = 0; k < HID; k++) {
            float wa = w0[k], wb = w1[k];
            float va = ha[k], vb = hb[k];
            a00 = fmaf(wa, va, a00);
            a01 = fmaf(wa, vb, a01);
            a10 = fmaf(wb, va, a10);
            a11 = fmaf(wb, vb, a11);
        }
        // add xg (already has b_ih + b_hh) and publish to gsm
        {
            const size_t xt = (size_t)t * BATCH * (4*HID);
            int g0 = (r0 & 3) * HID + n0 + (r0 >> 2);
            int g1 = (r1 & 3) * HID + n0 + (r1 >> 2);
            gsm[r0*33 + b0] = a00 + g_xg[xt + (size_t)b0 * (4*HID) + g0];
            gsm[r0*33 + b1] = a01 + g_xg[xt + (size_t)b1 * (4*HID) + g0];
            gsm[r1*33 + b0] = a10 + g_xg[xt + (size_t)b0 * (4*HID) + g1];
            gsm[r1*33 + b1] = a11 + g_xg[xt + (size_t)b1 * (4*HID) + g1];
        }
        __syncthreads();

        // phase C: each of the 128 threads owns one (unit, batch) cell
        {
            float iv = gsm[(cu*4 + 0)*33 + cb];
            float fv = gsm[(cu*4 + 1)*33 + cb];
            float gv = gsm[(cu*4 + 2)*33 + cb];
            float ov = gsm[(cu*4 + 3)*33 + cb];
            iv = 1.f / (1.f + __expf(-iv));
            fv = 1.f / (1.f + __expf(-fv));
            ov = 1.f / (1.f + __expf(-ov));
            gv = tanhf(gv);
            c_reg = fv * c_reg + iv * gv;
            float hn = ov * tanhf(c_reg);
            int nidx = n0 + cu;
            __stcg(&g_hping[(t + 1) & 1][cb * HID + nidx], hn);
            g_hall[((size_t)t * BATCH + cb) * HID + nidx] = hn;
        }
        grid_barrier((unsigned)((t + 1) * NBLK_LSTM));
    }
}

// ---------------------------------------------------------------------------
// launch
// ---------------------------------------------------------------------------
extern "C" void kernel_launch(void* const* d_in, const int* in_sizes, int n_in,
                              void* d_out, int out_size) {
    const float* features  = (const float*)d_in[0];
    const int*   reports   = (const int*)  d_in[1];
    const float* emb_table = (const float*)d_in[2];
    const float* fc_w      = (const float*)d_in[3];
    const float* fc_b      = (const float*)d_in[4];
    const float* W_ih      = (const float*)d_in[5];
    const float* b_ih      = (const float*)d_in[6];
    const float* W_hh      = (const float*)d_in[7];
    const float* b_hh      = (const float*)d_in[8];
    const float* Wv        = (const float*)d_in[9];
    const float* bv        = (const float*)d_in[10];
    float* out = (float*)d_out;

    void *p_xg = nullptr, *p_hall = nullptr, *p_tok = nullptr;
    cudaGetSymbolAddress(&p_xg,   g_xg);
    cudaGetSymbolAddress(&p_hall, g_hall);
    cudaGetSymbolAddress(&p_tok,  g_tok);

    const int lstm_smem = (16*512 + 32*513 + 16*33) * (int)sizeof(float);
    cudaFuncSetAttribute(lstm_kernel, cudaFuncAttributeMaxDynamicSharedMemorySize, lstm_smem);

    // 1) tokens + barrier reset
    prep_kernel<<<(M_ROWS + 255) / 256, 256>>>(reports);
    // 2) avg-pool
    pool_kernel<<<(BATCH * FEAT + 255) / 256, 256>>>(features);
    // 3) h0
    h0_kernel<<<(BATCH * HID + 255) / 256, 256>>>(fc_w, fc_b);
    // 4) xg = gather(emb, tok) @ W_ih^T + b_ih + b_hh   (M=3200, N=2048, K=256)
    gemm_kernel<true, false><<<dim3(4*HID/128, M_ROWS/128), 256>>>(
        emb_table, W_ih, b_ih, b_hh, (float*)p_xg, 4*HID, EMB, (const int*)p_tok);
    // 5) LSTM recurrence (persistent, grid barrier per step)
    lstm_kernel<<<NBLK_LSTM, 128, lstm_smem>>>(W_hh);
    // 6) logits = hall @ Wv^T + bv, permuted to (B, T, VOCAB)  (M=3200, N=32000, K=512)
    gemm_kernel<false, true><<<dim3(VOCAB/128, M_ROWS/128), 256>>>(
        (const float*)p_hall, Wv, bv, nullptr, out, VOCAB, HID, nullptr);
}

// round 4
// speedup vs baseline: 1.4542x; 1.4542x over previous
#include <cuda_runtime.h>
#include <cuda_bf16.h>
#include <cstdint>
#include <cstddef>

#define VOCAB 32000
#define EMB   256
#define HID   512
#define FEAT  1024
#define BATCH 32
#define TT    100
#define M_ROWS (TT*BATCH)      // 3200
#define NBLK_LSTM 128

// ---------------------------------------------------------------------------
// device scratch (static allocations only — no cudaMalloc allowed)
// ---------------------------------------------------------------------------
__device__ float g_pooled[BATCH*FEAT];
__device__ float g_xg[(size_t)M_ROWS * 4 * HID];          // x@W_ih^T + b_ih + b_hh
__device__ float g_hall[(size_t)M_ROWS * HID];            // h_t rows, m = t*32+b
__device__ float g_hping[2][BATCH*HID];
__device__ int   g_tok[M_ROWS];
__device__ unsigned g_barrier;

// bf16 split buffers for the tensor-core vocab GEMM
__device__ __nv_bfloat16 g_wv_hi[(size_t)VOCAB * HID];
__device__ __nv_bfloat16 g_wv_lo[(size_t)VOCAB * HID];
__device__ __nv_bfloat16 g_h_hi[(size_t)M_ROWS * HID];
__device__ __nv_bfloat16 g_h_lo[(size_t)M_ROWS * HID];

// ---------------------------------------------------------------------------
// helpers
// ---------------------------------------------------------------------------
__device__ __forceinline__ uint32_t smem_u32(const void* p) {
    uint32_t a;
    asm("{ .reg .u64 t; cvta.to.shared.u64 t, %1; cvt.u32.u64 %0, t; }" : "=r"(a) : "l"(p));
    return a;
}
__device__ __forceinline__ void cp_async16(uint32_t dst, const void* src) {
    asm volatile("cp.async.cg.shared.global [%0], [%1], 16;" :: "r"(dst), "l"(src) : "memory");
}
#define CP_ASYNC_COMMIT() asm volatile("cp.async.commit_group;" ::: "memory")
#define CP_ASYNC_WAIT(n)  asm volatile("cp.async.wait_group %0;" :: "n"(n) : "memory")

__device__ __forceinline__ void ldsm_x4(uint32_t& r0, uint32_t& r1, uint32_t& r2, uint32_t& r3,
                                        uint32_t addr) {
    asm volatile("ldmatrix.sync.aligned.m8n8.x4.shared.b16 {%0,%1,%2,%3}, [%4];"
                 : "=r"(r0), "=r"(r1), "=r"(r2), "=r"(r3) : "r"(addr));
}
__device__ __forceinline__ void mma_bf16(float* c, uint32_t a0, uint32_t a1, uint32_t a2, uint32_t a3,
                                         uint32_t b0, uint32_t b1) {
    asm volatile("mma.sync.aligned.m16n8k16.row.col.f32.bf16.bf16.f32 "
                 "{%0,%1,%2,%3}, {%4,%5,%6,%7}, {%8,%9}, {%0,%1,%2,%3};"
                 : "+f"(c[0]), "+f"(c[1]), "+f"(c[2]), "+f"(c[3])
                 : "r"(a0), "r"(a1), "r"(a2), "r"(a3), "r"(b0), "r"(b1));
}

// packed fp32x2 FMA (gates GEMM)
__device__ __forceinline__ unsigned long long pack2(float x, float y) {
    unsigned long long r;
    asm("mov.b64 %0, {%1, %2};" : "=l"(r) : "r"(__float_as_uint(x)), "r"(__float_as_uint(y)));
    return r;
}
__device__ __forceinline__ void ffma2(unsigned long long& d, unsigned long long a, unsigned long long b) {
    asm("fma.rn.f32x2 %0, %1, %2, %3;" : "=l"(d) : "l"(a), "l"(b), "l"(d));
}

// ---------------------------------------------------------------------------
// prep / pool / h0 / split
// ---------------------------------------------------------------------------
__global__ void prep_kernel(const int* __restrict__ reports) {
    int i = blockIdx.x * blockDim.x + threadIdx.x;
    if (i == 0) g_barrier = 0u;
    if (i < M_ROWS) {
        int t = i >> 5, b = i & 31;
        g_tok[i] = (t == 0) ? 1 : reports[b * TT + (t - 1)];
    }
}

__global__ void pool_kernel(const float* __restrict__ feat) {
    int i = blockIdx.x * blockDim.x + threadIdx.x;
    if (i < BATCH * FEAT) {
        const float* p = feat + (size_t)i * 49;
        float s = 0.f;
        #pragma unroll
        for (int j = 0; j < 49; j++) s += p[j];
        g_pooled[i] = s * (1.f / 49.f);
    }
}

__global__ void h0_kernel(const float* __restrict__ fc_w, const float* __restrict__ fc_b) {
    int i = blockIdx.x * blockDim.x + threadIdx.x;
    if (i >= BATCH * HID) return;
    int b = i >> 9, j = i & 511;
    const float* pw = fc_w + (size_t)j * FEAT;
    const float* pp = g_pooled + (size_t)b * FEAT;
    float acc = fc_b[j];
    #pragma unroll 4
    for (int k = 0; k < FEAT; k++) acc = fmaf(pw[k], pp[k], acc);
    g_hping[0][b * HID + j] = acc;
}

__global__ void split_kernel(const float* __restrict__ src,
                             __nv_bfloat16* __restrict__ hi,
                             __nv_bfloat16* __restrict__ lo, int n4) {
    int i = blockIdx.x * blockDim.x + threadIdx.x;
    if (i >= n4) return;
    float4 v = reinterpret_cast<const float4*>(src)[i];
    float xs[4] = {v.x, v.y, v.z, v.w};
    __nv_bfloat16 h[4], l[4];
    #pragma unroll
    for (int j = 0; j < 4; j++) {
        h[j] = __float2bfloat16(xs[j]);
        l[j] = __float2bfloat16(xs[j] - __bfloat162float(h[j]));
    }
    reinterpret_cast<__nv_bfloat162*>(hi)[i*2]   = __nv_bfloat162(h[0], h[1]);
    reinterpret_cast<__nv_bfloat162*>(hi)[i*2+1] = __nv_bfloat162(h[2], h[3]);
    reinterpret_cast<__nv_bfloat162*>(lo)[i*2]   = __nv_bfloat162(l[0], l[1]);
    reinterpret_cast<__nv_bfloat162*>(lo)[i*2+1] = __nv_bfloat162(l[2], l[3]);
}

// ---------------------------------------------------------------------------
// SIMT fp32 GEMM (gates): C[M,N] = gather(A,m) . B[n] + bias0 + bias1
// ---------------------------------------------------------------------------
__global__ __launch_bounds__(256)
void gemm_gates_kernel(const float* __restrict__ Asrc, const float* __restrict__ Bsrc,
                       const float* __restrict__ bias0, const float* __restrict__ bias1,
                       float* __restrict__ C, int N, int K, const int* __restrict__ gidx)
{
    __shared__ float As[16 * 132];
    __shared__ float Bs[16 * 132];
    const int tid = threadIdx.x;
    const int n0 = blockIdx.x * 128;
    const int m0 = blockIdx.y * 128;
    const int ty = tid >> 4;
    const int tx = tid & 15;

    unsigned long long acc[8][4];
    #pragma unroll
    for (int i = 0; i < 8; i++)
        #pragma unroll
        for (int j = 0; j < 4; j++) acc[i][j] = 0ull;

    const int ml = tid >> 2;
    const int kq = (tid & 3) * 4;
    const float* arow0 = Asrc + (size_t)gidx[m0 + ml] * K;
    const float* arow1 = Asrc + (size_t)gidx[m0 + ml + 64] * K;
    const float* brow0 = Bsrc + (size_t)(n0 + ml) * K;
    const float* brow1 = Bsrc + (size_t)(n0 + ml + 64) * K;

    for (int k0 = 0; k0 < K; k0 += 16) {
        float4 a0  = *reinterpret_cast<const float4*>(arow0 + k0 + kq);
        float4 a1  = *reinterpret_cast<const float4*>(arow1 + k0 + kq);
        float4 bb0 = *reinterpret_cast<const float4*>(brow0 + k0 + kq);
        float4 bb1 = *reinterpret_cast<const float4*>(brow1 + k0 + kq);
        __syncthreads();
        As[(kq+0)*132 + ml] = a0.x;  As[(kq+1)*132 + ml] = a0.y;
        As[(kq+2)*132 + ml] = a0.z;  As[(kq+3)*132 + ml] = a0.w;
        As[(kq+0)*132 + ml+64] = a1.x;  As[(kq+1)*132 + ml+64] = a1.y;
        As[(kq+2)*132 + ml+64] = a1.z;  As[(kq+3)*132 + ml+64] = a1.w;
        Bs[(kq+0)*132 + ml] = bb0.x; Bs[(kq+1)*132 + ml] = bb0.y;
        Bs[(kq+2)*132 + ml] = bb0.z; Bs[(kq+3)*132 + ml] = bb0.w;
        Bs[(kq+0)*132 + ml+64] = bb1.x; Bs[(kq+1)*132 + ml+64] = bb1.y;
        Bs[(kq+2)*132 + ml+64] = bb1.z; Bs[(kq+3)*132 + ml+64] = bb1.w;
        __syncthreads();

        #pragma unroll
        for (int kk = 0; kk < 16; kk++) {
            const float* ar = As + kk*132 + ty*8;
            const float* br = Bs + kk*132 + tx*8;
            float4 av0 = *reinterpret_cast<const float4*>(ar);
            float4 av1 = *reinterpret_cast<const float4*>(ar + 4);
            float4 bv0 = *reinterpret_cast<const float4*>(br);
            float4 bv1 = *reinterpret_cast<const float4*>(br + 4);
            unsigned long long bp0 = pack2(bv0.x, bv0.y);
            unsigned long long bp1 = pack2(bv0.z, bv0.w);
            unsigned long long bp2 = pack2(bv1.x, bv1.y);
            unsigned long long bp3 = pack2(bv1.z, bv1.w);
            float aa[8] = {av0.x, av0.y, av0.z, av0.w, av1.x, av1.y, av1.z, av1.w};
            #pragma unroll
            for (int i = 0; i < 8; i++) {
                unsigned long long ap = pack2(aa[i], aa[i]);
                ffma2(acc[i][0], ap, bp0);
                ffma2(acc[i][1], ap, bp1);
                ffma2(acc[i][2], ap, bp2);
                ffma2(acc[i][3], ap, bp3);
            }
        }
    }

    float bias[8];
    #pragma unroll
    for (int j = 0; j < 8; j++) {
        int n = n0 + tx*8 + j;
        bias[j] = bias0[n] + bias1[n];
    }
    #pragma unroll
    for (int i = 0; i < 8; i++) {
        int m = m0 + ty*8 + i;
        size_t base = (size_t)m * (size_t)N + (size_t)(n0 + tx*8);
        float o[8];
        #pragma unroll
        for (int j = 0; j < 4; j++) {
            o[2*j]   = __uint_as_float((unsigned)(acc[i][j]))       + bias[2*j];
            o[2*j+1] = __uint_as_float((unsigned)(acc[i][j] >> 32)) + bias[2*j+1];
        }
        *reinterpret_cast<float4*>(C + base)     = make_float4(o[0], o[1], o[2], o[3]);
        *reinterpret_cast<float4*>(C + base + 4) = make_float4(o[4], o[5], o[6], o[7]);
    }
}

// ---------------------------------------------------------------------------
// grid barrier
// ---------------------------------------------------------------------------
__device__ __forceinline__ void grid_barrier(unsigned target) {
    __syncthreads();
    __threadfence();
    if (threadIdx.x == 0) {
        atomicAdd(&g_barrier, 1u);
        while (*((volatile unsigned*)&g_barrier) < target) { __nanosleep(64); }
    }
    __syncthreads();
    __threadfence();
}

// ---------------------------------------------------------------------------
// persistent LSTM recurrence (unchanged — 450us, revisit later)
// ---------------------------------------------------------------------------
__global__ __launch_bounds__(128)
void lstm_kernel(const float* __restrict__ Whh) {
    extern __shared__ float sm[];
    float* ws  = sm;
    float* hs  = sm + 16*512;
    float* gsm = sm + 16*512 + 32*513;

    const int tid = threadIdx.x;
    const int n0  = blockIdx.x * 4;

    for (int lr = 0; lr < 16; lr++) {
        int u = lr >> 2, g = lr & 3;
        const float* src = Whh + (size_t)(g * HID + n0 + u) * HID;
        for (int k = tid; k < HID; k += 128) ws[lr * HID + k] = src[k];
    }

    const int rp = tid >> 4;
    const int r0 = rp * 2, r1 = r0 + 1;
    const int bp = tid & 15;
    const int b0 = bp * 2, b1 = b0 + 1;
    const int cu = tid >> 5;
    const int cb = tid & 31;
    float c_reg = 0.f;

    __syncthreads();

    for (int t = 0; t < TT; t++) {
        const float* hin = g_hping[t & 1];
        for (int i = tid; i < BATCH * (HID/4); i += 128) {
            int b  = i >> 7;
            int kk = (i & 127) * 4;
            float4 v = __ldcg(reinterpret_cast<const float4*>(hin + b * HID + kk));
            float* d = hs + b * 513 + kk;
            d[0] = v.x; d[1] = v.y; d[2] = v.z; d[3] = v.w;
        }
        __syncthreads();

        const float* w0 = ws + r0 * HID;
        const float* w1 = ws + r1 * HID;
        const float* ha = hs + b0 * 513;
        const float* hb = hs + b1 * 513;
        float a00 = 0.f, a01 = 0.f, a10 = 0.f, a11 = 0.f;
        #pragma unroll 8
        for (int k = 0; k < HID; k++) {
            float wa = w0[k], wb = w1[k];
            float va = ha[k], vb = hb[k];
            a00 = fmaf(wa, va, a00);
            a01 = fmaf(wa, vb, a01);
            a10 = fmaf(wb, va, a10);
            a11 = fmaf(wb, vb, a11);
        }
        {
            const size_t xt = (size_t)t * BATCH * (4*HID);
            int g0 = (r0 & 3) * HID + n0 + (r0 >> 2);
            int g1 = (r1 & 3) * HID + n0 + (r1 >> 2);
            gsm[r0*33 + b0] = a00 + g_xg[xt + (size_t)b0 * (4*HID) + g0];
            gsm[r0*33 + b1] = a01 + g_xg[xt + (size_t)b1 * (4*HID) + g0];
            gsm[r1*33 + b0] = a10 + g_xg[xt + (size_t)b0 * (4*HID) + g1];
            gsm[r1*33 + b1] = a11 + g_xg[xt + (size_t)b1 * (4*HID) + g1];
        }
        __syncthreads();

        {
            float iv = gsm[(cu*4 + 0)*33 + cb];
            float fv = gsm[(cu*4 + 1)*33 + cb];
            float gv = gsm[(cu*4 + 2)*33 + cb];
            float ov = gsm[(cu*4 + 3)*33 + cb];
            iv = 1.f / (1.f + __expf(-iv));
            fv = 1.f / (1.f + __expf(-fv));
            ov = 1.f / (1.f + __expf(-ov));
            gv = tanhf(gv);
            c_reg = fv * c_reg + iv * gv;
            float hn = ov * tanhf(c_reg);
            int nidx = n0 + cu;
            __stcg(&g_hping[(t + 1) & 1][cb * HID + nidx], hn);
            g_hall[((size_t)t * BATCH + cb) * HID + nidx] = hn;
        }
        grid_barrier((unsigned)((t + 1) * NBLK_LSTM));
    }
}

// ---------------------------------------------------------------------------
// Tensor-core vocab GEMM via mma.sync bf16 (family-portable PTX, no tcgen05).
// out[b][t][n] = hall[m=t*32+b] . Wv[n] + bv[n]
// D += Ahi*Bhi + Ahi*Blo + Alo*Bhi  (fp32 accum)
// CTA tile 128x128, K-chunk 64, 8 warps (2x4), warp tile 64x32.
// SMEM stage 64KB (Ahi|Alo|Bhi|Blo 16KB each), 2 stages, cp.async pipeline.
// Swizzle: 128B rows, 16B chunk c stored at c ^ (row&7).
// ---------------------------------------------------------------------------
#define VG_STAGE 65536

__global__ __launch_bounds__(256)
void gemm_vocab_mma_kernel(const float* __restrict__ bv, float* __restrict__ out)
{
    extern __shared__ char vsm[];
    const uint32_t smem = smem_u32(vsm);

    const int tid  = threadIdx.x;
    const int wid  = tid >> 5;
    const int lane = tid & 31;
    const int wm   = wid >> 2;          // 0..1  (64-row slabs)
    const int wn   = wid & 3;           // 0..3  (32-col slabs)
    const int n0   = blockIdx.x * 128;
    const int m0   = blockIdx.y * 128;

    float acc[4][4][4];                 // [mt][nt(n8)][frag]
    #pragma unroll
    for (int i = 0; i < 4; i++)
        #pragma unroll
        for (int j = 0; j < 4; j++)
            #pragma unroll
            for (int q = 0; q < 4; q++) acc[i][j][q] = 0.f;

    // ---- loader lambda (16 cp.async of 16B per thread per chunk) ----
    auto load_chunk = [&](int chunk) {
        const uint32_t stage = smem + (uint32_t)(chunk & 1) * VG_STAGE;
        const int kbase = chunk * 64;
        #pragma unroll
        for (int j = 0; j < 16; j++) {
            int i = tid + j * 256;          // 0..4095
            int region = i >> 10;           // 0 Ahi, 1 Alo, 2 Bhi, 3 Blo
            int r  = (i >> 3) & 127;
            int cc = i & 7;
            const __nv_bfloat16* gb;
            int grow;
            if (region == 0)      { gb = g_h_hi;  grow = m0 + r; }
            else if (region == 1) { gb = g_h_lo;  grow = m0 + r; }
            else if (region == 2) { gb = g_wv_hi; grow = n0 + r; }
            else                  { gb = g_wv_lo; grow = n0 + r; }
            const void* src = gb + (size_t)grow * HID + kbase + cc * 8;
            uint32_t dst = stage + (uint32_t)region * 16384u
                         + (uint32_t)(r * 128) + (uint32_t)(((cc ^ (r & 7)) * 16));
            cp_async16(dst, src);
        }
        CP_ASYNC_COMMIT();
    };

    load_chunk(0);

    for (int chunk = 0; chunk < 8; chunk++) {
        if (chunk + 1 < 8) load_chunk(chunk + 1);
        if (chunk + 1 < 8) { CP_ASYNC_WAIT(1); } else { CP_ASYNC_WAIT(0); }
        __syncthreads();

        const uint32_t stage = smem + (uint32_t)(chunk & 1) * VG_STAGE;
        const uint32_t aBase = stage;               // Ahi
        const uint32_t bBase = stage + 32768u;      // Bhi

        #pragma unroll
        for (int ks = 0; ks < 4; ks++) {
            // A fragments: 4 m-tiles x {hi,lo}
            uint32_t ah[4][4], al[4][4];
            #pragma unroll
            for (int mt = 0; mt < 4; mt++) {
                int row = wm * 64 + mt * 16 + (lane & 7) + ((lane >> 3) & 1) * 8;
                int ch  = ks * 2 + (lane >> 4);
                uint32_t off = (uint32_t)(row * 128) + (uint32_t)((ch ^ (row & 7)) * 16);
                ldsm_x4(ah[mt][0], ah[mt][1], ah[mt][2], ah[mt][3], aBase + off);
                ldsm_x4(al[mt][0], al[mt][1], al[mt][2], al[mt][3], aBase + 16384u + off);
            }
            // B fragments: 2 n16-pairs x {hi,lo}
            uint32_t bh[4][2], bl[4][2];
            #pragma unroll
            for (int p = 0; p < 2; p++) {
                int g   = lane >> 3;
                int row = wn * 32 + p * 16 + (g & 1) * 8 + (lane & 7);
                int ch  = ks * 2 + (g >> 1);
                uint32_t off = (uint32_t)(row * 128) + (uint32_t)((ch ^ (row & 7)) * 16);
                uint32_t r0, r1, r2, r3;
                ldsm_x4(r0, r1, r2, r3, bBase + off);
                bh[p*2+0][0] = r0; bh[p*2+0][1] = r2;
                bh[p*2+1][0] = r1; bh[p*2+1][1] = r3;
                ldsm_x4(r0, r1, r2, r3, bBase + 16384u + off);
                bl[p*2+0][0] = r0; bl[p*2+0][1] = r2;
                bl[p*2+1][0] = r1; bl[p*2+1][1] = r3;
            }
            // MMAs: 4m x 4n x 3 products
            #pragma unroll
            for (int mt = 0; mt < 4; mt++) {
                #pragma unroll
                for (int nt = 0; nt < 4; nt++) {
                    mma_bf16(acc[mt][nt], ah[mt][0], ah[mt][1], ah[mt][2], ah[mt][3],
                             bh[nt][0], bh[nt][1]);
                    mma_bf16(acc[mt][nt], ah[mt][0], ah[mt][1], ah[mt][2], ah[mt][3],
                             bl[nt][0], bl[nt][1]);
                    mma_bf16(acc[mt][nt], al[mt][0], al[mt][1], al[mt][2], al[mt][3],
                             bh[nt][0], bh[nt][1]);
                }
            }
        }
        __syncthreads();
    }

    // ---- epilogue: permuted rows, +bias, float2 stores ----
    #pragma unroll
    for (int mt = 0; mt < 4; mt++) {
        int gm0 = m0 + wm * 64 + mt * 16 + (lane >> 2);
        int gm1 = gm0 + 8;
        size_t ob0 = ((size_t)(gm0 & 31) * TT + (size_t)(gm0 >> 5)) * (size_t)VOCAB;
        size_t ob1 = ((size_t)(gm1 & 31) * TT + (size_t)(gm1 >> 5)) * (size_t)VOCAB;
        #pragma unroll
        for (int nt = 0; nt < 4; nt++) {
            int gn = n0 + wn * 32 + nt * 8 + (lane & 3) * 2;
            float bv0 = __ldg(bv + gn), bv1 = __ldg(bv + gn + 1);
            float2 v0 = make_float2(acc[mt][nt][0] + bv0, acc[mt][nt][1] + bv1);
            float2 v1 = make_float2(acc[mt][nt][2] + bv0, acc[mt][nt][3] + bv1);
            *reinterpret_cast<float2*>(out + ob0 + gn) = v0;
            *reinterpret_cast<float2*>(out + ob1 + gn) = v1;
        }
    }
}

// ---------------------------------------------------------------------------
// launch
// ---------------------------------------------------------------------------
extern "C" void kernel_launch(void* const* d_in, const int* in_sizes, int n_in,
                              void* d_out, int out_size) {
    const float* features  = (const float*)d_in[0];
    const int*   reports   = (const int*)  d_in[1];
    const float* emb_table = (const float*)d_in[2];
    const float* fc_w      = (const float*)d_in[3];
    const float* fc_b      = (const float*)d_in[4];
    const float* W_ih      = (const float*)d_in[5];
    const float* b_ih      = (const float*)d_in[6];
    const float* W_hh      = (const float*)d_in[7];
    const float* b_hh      = (const float*)d_in[8];
    const float* Wv        = (const float*)d_in[9];
    const float* bv        = (const float*)d_in[10];
    float* out = (float*)d_out;

    void *p_xg = nullptr, *p_hall = nullptr, *p_tok = nullptr;
    void *p_wvh = nullptr, *p_wvl = nullptr, *p_hh = nullptr, *p_hl = nullptr;
    cudaGetSymbolAddress(&p_xg,   g_xg);
    cudaGetSymbolAddress(&p_hall, g_hall);
    cudaGetSymbolAddress(&p_tok,  g_tok);
    cudaGetSymbolAddress(&p_wvh,  g_wv_hi);
    cudaGetSymbolAddress(&p_wvl,  g_wv_lo);
    cudaGetSymbolAddress(&p_hh,   g_h_hi);
    cudaGetSymbolAddress(&p_hl,   g_h_lo);

    const int lstm_smem = (16*512 + 32*513 + 16*33) * (int)sizeof(float);
    cudaFuncSetAttribute(lstm_kernel, cudaFuncAttributeMaxDynamicSharedMemorySize, lstm_smem);
    const int vg_smem = 2 * VG_STAGE;   // 128 KB
    cudaFuncSetAttribute(gemm_vocab_mma_kernel, cudaFuncAttributeMaxDynamicSharedMemorySize, vg_smem);

    // 1) tokens + barrier reset
    prep_kernel<<<(M_ROWS + 255) / 256, 256>>>(reports);
    // 2) avg-pool
    pool_kernel<<<(BATCH * FEAT + 255) / 256, 256>>>(features);
    // 3) h0
    h0_kernel<<<(BATCH * HID + 255) / 256, 256>>>(fc_w, fc_b);
    // 4) split Wv into bf16 hi/lo (overlaps nothing but is off the critical LSTM path)
    {
        int n4 = VOCAB * HID / 4;
        split_kernel<<<(n4 + 255) / 256, 256>>>(Wv, (__nv_bfloat16*)p_wvh, (__nv_bfloat16*)p_wvl, n4);
    }
    // 5) xg = gather(emb, tok) @ W_ih^T + b_ih + b_hh
    gemm_gates_kernel<<<dim3(4*HID/128, M_ROWS/128), 256>>>(
        emb_table, W_ih, b_ih, b_hh, (float*)p_xg, 4*HID, EMB, (const int*)p_tok);
    // 6) LSTM recurrence
    lstm_kernel<<<NBLK_LSTM, 128, lstm_smem>>>(W_hh);
    // 7) split hall into bf16 hi/lo
    {
        int n4 = M_ROWS * HID / 4;
        split_kernel<<<(n4 + 255) / 256, 256>>>((const float*)p_hall,
                                                (__nv_bfloat16*)p_hh, (__nv_bfloat16*)p_hl, n4);
    }
    // 8) logits via tensor cores (permuted epilogue -> (B,T,VOCAB))
    gemm_vocab_mma_kernel<<<dim3(VOCAB/128, M_ROWS/128), 256, vg_smem>>>(bv, out);
}

// round 5
// speedup vs baseline: 1.7558x; 1.2074x over previous
#include <cuda_runtime.h>
#include <cuda_bf16.h>
#include <cstdint>
#include <cstddef>

#define VOCAB 32000
#define EMB   256
#define HID   512
#define FEAT  1024
#define BATCH 32
#define TT    100
#define M_ROWS (TT*BATCH)      // 3200
#define NBLK_LSTM 128
typedef unsigned long long ull;

// ---------------------------------------------------------------------------
// device scratch
// ---------------------------------------------------------------------------
__device__ float g_pooled[BATCH*FEAT];
__device__ float g_xg[(size_t)M_ROWS * 4 * HID];
__device__ float g_hall[(size_t)M_ROWS * HID];
__device__ float g_hping[2][BATCH*HID];
__device__ int   g_tok[M_ROWS];
__device__ unsigned g_barrier;

__device__ __nv_bfloat16 g_wv_hi[(size_t)VOCAB * HID];
__device__ __nv_bfloat16 g_wv_lo[(size_t)VOCAB * HID];
__device__ __nv_bfloat16 g_h_hi[(size_t)M_ROWS * HID];
__device__ __nv_bfloat16 g_h_lo[(size_t)M_ROWS * HID];

// ---------------------------------------------------------------------------
// helpers
// ---------------------------------------------------------------------------
__device__ __forceinline__ uint32_t smem_u32(const void* p) {
    uint32_t a;
    asm("{ .reg .u64 t; cvta.to.shared.u64 t, %1; cvt.u32.u64 %0, t; }" : "=r"(a) : "l"(p));
    return a;
}
__device__ __forceinline__ void cp_async16(uint32_t dst, const void* src) {
    asm volatile("cp.async.cg.shared.global [%0], [%1], 16;" :: "r"(dst), "l"(src) : "memory");
}
#define CP_ASYNC_COMMIT() asm volatile("cp.async.commit_group;" ::: "memory")
#define CP_ASYNC_WAIT(n)  asm volatile("cp.async.wait_group %0;" :: "n"(n) : "memory")

__device__ __forceinline__ void ldsm_x4(uint32_t& r0, uint32_t& r1, uint32_t& r2, uint32_t& r3,
                                        uint32_t addr) {
    asm volatile("ldmatrix.sync.aligned.m8n8.x4.shared.b16 {%0,%1,%2,%3}, [%4];"
                 : "=r"(r0), "=r"(r1), "=r"(r2), "=r"(r3) : "r"(addr));
}
__device__ __forceinline__ void mma_bf16(float* c, uint32_t a0, uint32_t a1, uint32_t a2, uint32_t a3,
                                         uint32_t b0, uint32_t b1) {
    asm volatile("mma.sync.aligned.m16n8k16.row.col.f32.bf16.bf16.f32 "
                 "{%0,%1,%2,%3}, {%4,%5,%6,%7}, {%8,%9}, {%0,%1,%2,%3};"
                 : "+f"(c[0]), "+f"(c[1]), "+f"(c[2]), "+f"(c[3])
                 : "r"(a0), "r"(a1), "r"(a2), "r"(a3), "r"(b0), "r"(b1));
}

__device__ __forceinline__ ull pack2(float x, float y) {
    ull r;
    asm("mov.b64 %0, {%1, %2};" : "=l"(r) : "r"(__float_as_uint(x)), "r"(__float_as_uint(y)));
    return r;
}
__device__ __forceinline__ void ffma2(ull& d, ull a, ull b) {
    asm("fma.rn.f32x2 %0, %1, %2, %3;" : "=l"(d) : "l"(a), "l"(b), "l"(d));
}
__device__ __forceinline__ float sum2(ull p) {
    return __uint_as_float((unsigned)p) + __uint_as_float((unsigned)(p >> 32));
}

// ---------------------------------------------------------------------------
// prep / pool / h0 / split
// ---------------------------------------------------------------------------
__global__ void prep_kernel(const int* __restrict__ reports) {
    int i = blockIdx.x * blockDim.x + threadIdx.x;
    if (i == 0) g_barrier = 0u;
    if (i < M_ROWS) {
        int t = i >> 5, b = i & 31;
        g_tok[i] = (t == 0) ? 1 : reports[b * TT + (t - 1)];
    }
}

__global__ void pool_kernel(const float* __restrict__ feat) {
    int i = blockIdx.x * blockDim.x + threadIdx.x;
    if (i < BATCH * FEAT) {
        const float* p = feat + (size_t)i * 49;
        float s = 0.f;
        #pragma unroll
        for (int j = 0; j < 49; j++) s += p[j];
        g_pooled[i] = s * (1.f / 49.f);
    }
}

__global__ void h0_kernel(const float* __restrict__ fc_w, const float* __restrict__ fc_b) {
    int i = blockIdx.x * blockDim.x + threadIdx.x;
    if (i >= BATCH * HID) return;
    int b = i >> 9, j = i & 511;
    const float* pw = fc_w + (size_t)j * FEAT;
    const float* pp = g_pooled + (size_t)b * FEAT;
    float acc = fc_b[j];
    #pragma unroll 4
    for (int k = 0; k < FEAT; k++) acc = fmaf(pw[k], pp[k], acc);
    g_hping[0][b * HID + j] = acc;
}

__global__ void split_kernel(const float* __restrict__ src,
                             __nv_bfloat16* __restrict__ hi,
                             __nv_bfloat16* __restrict__ lo, int n4) {
    int i = blockIdx.x * blockDim.x + threadIdx.x;
    if (i >= n4) return;
    float4 v = reinterpret_cast<const float4*>(src)[i];
    float xs[4] = {v.x, v.y, v.z, v.w};
    __nv_bfloat16 h[4], l[4];
    #pragma unroll
    for (int j = 0; j < 4; j++) {
        h[j] = __float2bfloat16(xs[j]);
        l[j] = __float2bfloat16(xs[j] - __bfloat162float(h[j]));
    }
    reinterpret_cast<__nv_bfloat162*>(hi)[i*2]   = __nv_bfloat162(h[0], h[1]);
    reinterpret_cast<__nv_bfloat162*>(hi)[i*2+1] = __nv_bfloat162(h[2], h[3]);
    reinterpret_cast<__nv_bfloat162*>(lo)[i*2]   = __nv_bfloat162(l[0], l[1]);
    reinterpret_cast<__nv_bfloat162*>(lo)[i*2+1] = __nv_bfloat162(l[2], l[3]);
}

// ---------------------------------------------------------------------------
// SIMT fp32 GEMM (gates)
// ---------------------------------------------------------------------------
__global__ __launch_bounds__(256)
void gemm_gates_kernel(const float* __restrict__ Asrc, const float* __restrict__ Bsrc,
                       const float* __restrict__ bias0, const float* __restrict__ bias1,
                       float* __restrict__ C, int N, int K, const int* __restrict__ gidx)
{
    __shared__ float As[16 * 132];
    __shared__ float Bs[16 * 132];
    const int tid = threadIdx.x;
    const int n0 = blockIdx.x * 128;
    const int m0 = blockIdx.y * 128;
    const int ty = tid >> 4;
    const int tx = tid & 15;

    ull acc[8][4];
    #pragma unroll
    for (int i = 0; i < 8; i++)
        #pragma unroll
        for (int j = 0; j < 4; j++) acc[i][j] = 0ull;

    const int ml = tid >> 2;
    const int kq = (tid & 3) * 4;
    const float* arow0 = Asrc + (size_t)gidx[m0 + ml] * K;
    const float* arow1 = Asrc + (size_t)gidx[m0 + ml + 64] * K;
    const float* brow0 = Bsrc + (size_t)(n0 + ml) * K;
    const float* brow1 = Bsrc + (size_t)(n0 + ml + 64) * K;

    for (int k0 = 0; k0 < K; k0 += 16) {
        float4 a0  = *reinterpret_cast<const float4*>(arow0 + k0 + kq);
        float4 a1  = *reinterpret_cast<const float4*>(arow1 + k0 + kq);
        float4 bb0 = *reinterpret_cast<const float4*>(brow0 + k0 + kq);
        float4 bb1 = *reinterpret_cast<const float4*>(brow1 + k0 + kq);
        __syncthreads();
        As[(kq+0)*132 + ml] = a0.x;  As[(kq+1)*132 + ml] = a0.y;
        As[(kq+2)*132 + ml] = a0.z;  As[(kq+3)*132 + ml] = a0.w;
        As[(kq+0)*132 + ml+64] = a1.x;  As[(kq+1)*132 + ml+64] = a1.y;
        As[(kq+2)*132 + ml+64] = a1.z;  As[(kq+3)*132 + ml+64] = a1.w;
        Bs[(kq+0)*132 + ml] = bb0.x; Bs[(kq+1)*132 + ml] = bb0.y;
        Bs[(kq+2)*132 + ml] = bb0.z; Bs[(kq+3)*132 + ml] = bb0.w;
        Bs[(kq+0)*132 + ml+64] = bb1.x; Bs[(kq+1)*132 + ml+64] = bb1.y;
        Bs[(kq+2)*132 + ml+64] = bb1.z; Bs[(kq+3)*132 + ml+64] = bb1.w;
        __syncthreads();

        #pragma unroll
        for (int kk = 0; kk < 16; kk++) {
            const float* ar = As + kk*132 + ty*8;
            const float* br = Bs + kk*132 + tx*8;
            float4 av0 = *reinterpret_cast<const float4*>(ar);
            float4 av1 = *reinterpret_cast<const float4*>(ar + 4);
            float4 bv0 = *reinterpret_cast<const float4*>(br);
            float4 bv1 = *reinterpret_cast<const float4*>(br + 4);
            ull bp0 = pack2(bv0.x, bv0.y);
            ull bp1 = pack2(bv0.z, bv0.w);
            ull bp2 = pack2(bv1.x, bv1.y);
            ull bp3 = pack2(bv1.z, bv1.w);
            float aa[8] = {av0.x, av0.y, av0.z, av0.w, av1.x, av1.y, av1.z, av1.w};
            #pragma unroll
            for (int i = 0; i < 8; i++) {
                ull ap = pack2(aa[i], aa[i]);
                ffma2(acc[i][0], ap, bp0);
                ffma2(acc[i][1], ap, bp1);
                ffma2(acc[i][2], ap, bp2);
                ffma2(acc[i][3], ap, bp3);
            }
        }
    }

    float bias[8];
    #pragma unroll
    for (int j = 0; j < 8; j++) {
        int n = n0 + tx*8 + j;
        bias[j] = bias0[n] + bias1[n];
    }
    #pragma unroll
    for (int i = 0; i < 8; i++) {
        int m = m0 + ty*8 + i;
        size_t base = (size_t)m * (size_t)N + (size_t)(n0 + tx*8);
        float o[8];
        #pragma unroll
        for (int j = 0; j < 4; j++) {
            o[2*j]   = __uint_as_float((unsigned)(acc[i][j]))       + bias[2*j];
            o[2*j+1] = __uint_as_float((unsigned)(acc[i][j] >> 32)) + bias[2*j+1];
        }
        *reinterpret_cast<float4*>(C + base)     = make_float4(o[0], o[1], o[2], o[3]);
        *reinterpret_cast<float4*>(C + base + 4) = make_float4(o[4], o[5], o[6], o[7]);
    }
}

// ---------------------------------------------------------------------------
// grid barrier
// ---------------------------------------------------------------------------
__device__ __forceinline__ void grid_barrier(unsigned target) {
    __syncthreads();
    __threadfence();
    if (threadIdx.x == 0) {
        atomicAdd(&g_barrier, 1u);
        while (*((volatile unsigned*)&g_barrier) < target) { __nanosleep(64); }
    }
    __syncthreads();
    __threadfence();
}

// ---------------------------------------------------------------------------
// persistent LSTM recurrence.
// 128 blocks x 128 threads, block owns 4 hidden units (16 gate rows).
// R5: phase B vectorized — LDS.128 over k, packed f32x2 FMA over k-pairs.
//     Lane remap: adjacent lanes share batch-pair (broadcast dedup).
// smem: ws 16*516 | hs 32*516 | gsm 16*33   (stride 516: 16B-aligned +
//       conflict-free float4 access for the lane map below)
// ---------------------------------------------------------------------------
#define WS_STRIDE 516
__global__ __launch_bounds__(128)
void lstm_kernel(const float* __restrict__ Whh) {
    extern __shared__ float sm[];
    float* ws  = sm;                          // 16*516
    float* hs  = sm + 16*WS_STRIDE;           // 32*516
    float* gsm = sm + 16*WS_STRIDE + 32*WS_STRIDE;  // 16*33

    const int tid = threadIdx.x;
    const int n0  = blockIdx.x * 4;

    // cache W_hh slice (row order lr = u*4+g)
    for (int lr = 0; lr < 16; lr++) {
        int u = lr >> 2, g = lr & 3;
        const float* src = Whh + (size_t)(g * HID + n0 + u) * HID;
        for (int k = tid; k < HID; k += 128) ws[lr * WS_STRIDE + k] = src[k];
    }

    // lane map: rp = row-pair (0..7), bp = batch-pair (0..15)
    // adjacent lanes share bp -> broadcast-deduped h loads, conflict-free LDS.128
    const int rp = (tid & 1) + ((tid >> 5) << 1);
    const int r0 = rp * 2, r1 = r0 + 1;       // local gate rows
    const int bp = (tid >> 1) & 15;
    const int b0 = bp * 2, b1 = b0 + 1;       // batches
    const int cu = tid >> 5;                  // phase-C unit 0..3
    const int cb = tid & 31;                  // phase-C batch
    float c_reg = 0.f;

    __syncthreads();

    for (int t = 0; t < TT; t++) {
        // phase A: h(ping) -> hs (stride 516)
        const float* hin = g_hping[t & 1];
        #pragma unroll 4
        for (int j = 0; j < 32; j++) {
            float4 v = __ldcg(reinterpret_cast<const float4*>(hin + j * HID + tid * 4));
            *reinterpret_cast<float4*>(hs + j * WS_STRIDE + tid * 4) = v;
        }
        __syncthreads();

        // phase B: 2 rows x 2 batches per thread; LDS.128 + f32x2 FMA
        const ulonglong2* w0 = reinterpret_cast<const ulonglong2*>(ws + r0 * WS_STRIDE);
        const ulonglong2* w1 = reinterpret_cast<const ulonglong2*>(ws + r1 * WS_STRIDE);
        const ulonglong2* ha = reinterpret_cast<const ulonglong2*>(hs + b0 * WS_STRIDE);
        const ulonglong2* hb = reinterpret_cast<const ulonglong2*>(hs + b1 * WS_STRIDE);
        ull p00 = 0ull, p01 = 0ull, p10 = 0ull, p11 = 0ull;
        #pragma unroll 8
        for (int k = 0; k < HID/4; k++) {
            ulonglong2 wa = w0[k], wb = w1[k];
            ulonglong2 va = ha[k], vb = hb[k];
            ffma2(p00, wa.x, va.x); ffma2(p00, wa.y, va.y);
            ffma2(p01, wa.x, vb.x); ffma2(p01, wa.y, vb.y);
            ffma2(p10, wb.x, va.x); ffma2(p10, wb.y, va.y);
            ffma2(p11, wb.x, vb.x); ffma2(p11, wb.y, vb.y);
        }
        float a00 = sum2(p00), a01 = sum2(p01), a10 = sum2(p10), a11 = sum2(p11);
        {
            const size_t xt = (size_t)t * BATCH * (4*HID);
            int g0 = (r0 & 3) * HID + n0 + (r0 >> 2);
            int g1 = (r1 & 3) * HID + n0 + (r1 >> 2);
            gsm[r0*33 + b0] = a00 + g_xg[xt + (size_t)b0 * (4*HID) + g0];
            gsm[r0*33 + b1] = a01 + g_xg[xt + (size_t)b1 * (4*HID) + g0];
            gsm[r1*33 + b0] = a10 + g_xg[xt + (size_t)b0 * (4*HID) + g1];
            gsm[r1*33 + b1] = a11 + g_xg[xt + (size_t)b1 * (4*HID) + g1];
        }
        __syncthreads();

        // phase C: one (unit, batch) cell per thread
        {
            float iv = gsm[(cu*4 + 0)*33 + cb];
            float fv = gsm[(cu*4 + 1)*33 + cb];
            float gv = gsm[(cu*4 + 2)*33 + cb];
            float ov = gsm[(cu*4 + 3)*33 + cb];
            iv = 1.f / (1.f + __expf(-iv));
            fv = 1.f / (1.f + __expf(-fv));
            ov = 1.f / (1.f + __expf(-ov));
            gv = tanhf(gv);
            c_reg = fv * c_reg + iv * gv;
            float hn = ov * tanhf(c_reg);
            int nidx = n0 + cu;
            __stcg(&g_hping[(t + 1) & 1][cb * HID + nidx], hn);
            g_hall[((size_t)t * BATCH + cb) * HID + nidx] = hn;
        }
        grid_barrier((unsigned)((t + 1) * NBLK_LSTM));
    }
}

// ---------------------------------------------------------------------------
// Tensor-core vocab GEMM (mma.sync bf16 split, family-portable PTX).
// out[b][t][n] = hall[m=t*32+b] . Wv[n] + bv[n]
// D += Ahi*Bhi + Ahi*Blo + Alo*Bhi
// R5: CTA tile 128x256, 8 warps (2x4), warp tile 64x64, K-chunk 64,
//     stage 96KB (Ahi 16|Alo 16|Bhi 32|Blo 32), 2 stages cp.async pipeline.
// ---------------------------------------------------------------------------
#define VG_STAGE 98304

__global__ __launch_bounds__(256)
void gemm_vocab_mma_kernel(const float* __restrict__ bv, float* __restrict__ out)
{
    extern __shared__ char vsm[];
    const uint32_t smem = smem_u32(vsm);

    const int tid  = threadIdx.x;
    const int wid  = tid >> 5;
    const int lane = tid & 31;
    const int wm   = wid >> 2;          // 0..1  (64-row slabs)
    const int wn   = wid & 3;           // 0..3  (64-col slabs)
    const int n0   = blockIdx.x * 256;
    const int m0   = blockIdx.y * 128;

    float acc[4][8][4];
    #pragma unroll
    for (int i = 0; i < 4; i++)
        #pragma unroll
        for (int j = 0; j < 8; j++)
            #pragma unroll
            for (int q = 0; q < 4; q++) acc[i][j][q] = 0.f;

    // loader: 24 cp.async of 16B per thread per chunk (6144 total)
    auto load_chunk = [&](int chunk) {
        const uint32_t stage = smem + (uint32_t)(chunk & 1) * VG_STAGE;
        const int kbase = chunk * 64;
        #pragma unroll
        for (int j = 0; j < 24; j++) {
            int i = tid + j * 256;          // 0..6143
            const __nv_bfloat16* gb;
            int grow;
            uint32_t doff;
            if (i < 2048) {                  // A: hi then lo, 128 rows x 8 chunks
                int dt = i >> 10;
                int r  = (i >> 3) & 127;
                int cc = i & 7;
                gb = dt ? g_h_lo : g_h_hi;
                grow = m0 + r;
                doff = (uint32_t)dt * 16384u + (uint32_t)(r * 128) + (uint32_t)(((cc ^ (r & 7)) * 16));
            } else {                         // B: hi then lo, 256 rows x 8 chunks
                int jj = i - 2048;
                int dt = jj >> 11;
                int r  = (jj >> 3) & 255;
                int cc = jj & 7;
                gb = dt ? g_wv_lo : g_wv_hi;
                grow = n0 + r;
                doff = 32768u + (uint32_t)dt * 32768u + (uint32_t)(r * 128) + (uint32_t)(((cc ^ (r & 7)) * 16));
            }
            cp_async16(stage + doff, gb + (size_t)grow * HID + kbase + (i & 7) * 8);
        }
        CP_ASYNC_COMMIT();
    };

    load_chunk(0);

    for (int chunk = 0; chunk < 8; chunk++) {
        if (chunk + 1 < 8) { load_chunk(chunk + 1); CP_ASYNC_WAIT(1); }
        else               { CP_ASYNC_WAIT(0); }
        __syncthreads();

        const uint32_t stage = smem + (uint32_t)(chunk & 1) * VG_STAGE;
        const uint32_t aBase = stage;               // Ahi (Alo at +16384)
        const uint32_t bBase = stage + 32768u;      // Bhi (Blo at +32768)

        #pragma unroll
        for (int ks = 0; ks < 4; ks++) {
            // A fragments: 4 m-tiles x {hi,lo}
            uint32_t ah[4][4], al[4][4];
            #pragma unroll
            for (int mt = 0; mt < 4; mt++) {
                int row = wm * 64 + mt * 16 + (lane & 7) + ((lane >> 3) & 1) * 8;
                int ch  = ks * 2 + (lane >> 4);
                uint32_t off = (uint32_t)(row * 128) + (uint32_t)((ch ^ (row & 7)) * 16);
                ldsm_x4(ah[mt][0], ah[mt][1], ah[mt][2], ah[mt][3], aBase + off);
                ldsm_x4(al[mt][0], al[mt][1], al[mt][2], al[mt][3], aBase + 16384u + off);
            }
            // B: process per 16-col group to bound register pressure
            #pragma unroll
            for (int p = 0; p < 4; p++) {
                int g   = lane >> 3;
                int row = wn * 64 + p * 16 + (g & 1) * 8 + (lane & 7);
                int ch  = ks * 2 + (g >> 1);
                uint32_t off = (uint32_t)(row * 128) + (uint32_t)((ch ^ (row & 7)) * 16);
                uint32_t bh[2][2], bl[2][2];
                {
                    uint32_t r0, r1, r2, r3;
                    ldsm_x4(r0, r1, r2, r3, bBase + off);
                    bh[0][0] = r0; bh[0][1] = r2;
                    bh[1][0] = r1; bh[1][1] = r3;
                    ldsm_x4(r0, r1, r2, r3, bBase + 32768u + off);
                    bl[0][0] = r0; bl[0][1] = r2;
                    bl[1][0] = r1; bl[1][1] = r3;
                }
                #pragma unroll
                for (int mt = 0; mt < 4; mt++) {
                    #pragma unroll
                    for (int q = 0; q < 2; q++) {
                        int nt = p * 2 + q;
                        mma_bf16(acc[mt][nt], ah[mt][0], ah[mt][1], ah[mt][2], ah[mt][3],
                                 bh[q][0], bh[q][1]);
                        mma_bf16(acc[mt][nt], ah[mt][0], ah[mt][1], ah[mt][2], ah[mt][3],
                                 bl[q][0], bl[q][1]);
                        mma_bf16(acc[mt][nt], al[mt][0], al[mt][1], al[mt][2], al[mt][3],
                                 bh[q][0], bh[q][1]);
                    }
                }
            }
        }
        __syncthreads();
    }

    // epilogue: permuted rows, +bias, float2 stores
    #pragma unroll
    for (int mt = 0; mt < 4; mt++) {
        int gm0 = m0 + wm * 64 + mt * 16 + (lane >> 2);
        int gm1 = gm0 + 8;
        size_t ob0 = ((size_t)(gm0 & 31) * TT + (size_t)(gm0 >> 5)) * (size_t)VOCAB;
        size_t ob1 = ((size_t)(gm1 & 31) * TT + (size_t)(gm1 >> 5)) * (size_t)VOCAB;
        #pragma unroll
        for (int nt = 0; nt < 8; nt++) {
            int gn = n0 + wn * 64 + nt * 8 + (lane & 3) * 2;
            float bv0 = __ldg(bv + gn), bv1 = __ldg(bv + gn + 1);
            float2 v0 = make_float2(acc[mt][nt][0] + bv0, acc[mt][nt][1] + bv1);
            float2 v1 = make_float2(acc[mt][nt][2] + bv0, acc[mt][nt][3] + bv1);
            *reinterpret_cast<float2*>(out + ob0 + gn) = v0;
            *reinterpret_cast<float2*>(out + ob1 + gn) = v1;
        }
    }
}

// ---------------------------------------------------------------------------
// launch
// ---------------------------------------------------------------------------
extern "C" void kernel_launch(void* const* d_in, const int* in_sizes, int n_in,
                              void* d_out, int out_size) {
    const float* features  = (const float*)d_in[0];
    const int*   reports   = (const int*)  d_in[1];
    const float* emb_table = (const float*)d_in[2];
    const float* fc_w      = (const float*)d_in[3];
    const float* fc_b      = (const float*)d_in[4];
    const float* W_ih      = (const float*)d_in[5];
    const float* b_ih      = (const float*)d_in[6];
    const float* W_hh      = (const float*)d_in[7];
    const float* b_hh      = (const float*)d_in[8];
    const float* Wv        = (const float*)d_in[9];
    const float* bv        = (const float*)d_in[10];
    float* out = (float*)d_out;

    void *p_xg = nullptr, *p_hall = nullptr, *p_tok = nullptr;
    void *p_wvh = nullptr, *p_wvl = nullptr, *p_hh = nullptr, *p_hl = nullptr;
    cudaGetSymbolAddress(&p_xg,   g_xg);
    cudaGetSymbolAddress(&p_hall, g_hall);
    cudaGetSymbolAddress(&p_tok,  g_tok);
    cudaGetSymbolAddress(&p_wvh,  g_wv_hi);
    cudaGetSymbolAddress(&p_wvl,  g_wv_lo);
    cudaGetSymbolAddress(&p_hh,   g_h_hi);
    cudaGetSymbolAddress(&p_hl,   g_h_lo);

    const int lstm_smem = (16*WS_STRIDE + 32*WS_STRIDE + 16*33) * (int)sizeof(float);
    cudaFuncSetAttribute(lstm_kernel, cudaFuncAttributeMaxDynamicSharedMemorySize, lstm_smem);
    const int vg_smem = 2 * VG_STAGE;   // 192 KB
    cudaFuncSetAttribute(gemm_vocab_mma_kernel, cudaFuncAttributeMaxDynamicSharedMemorySize, vg_smem);

    prep_kernel<<<(M_ROWS + 255) / 256, 256>>>(reports);
    pool_kernel<<<(BATCH * FEAT + 255) / 256, 256>>>(features);
    h0_kernel<<<(BATCH * HID + 255) / 256, 256>>>(fc_w, fc_b);
    {
        int n4 = VOCAB * HID / 4;
        split_kernel<<<(n4 + 255) / 256, 256>>>(Wv, (__nv_bfloat16*)p_wvh, (__nv_bfloat16*)p_wvl, n4);
    }
    gemm_gates_kernel<<<dim3(4*HID/128, M_ROWS/128), 256>>>(
        emb_table, W_ih, b_ih, b_hh, (float*)p_xg, 4*HID, EMB, (const int*)p_tok);
    lstm_kernel<<<NBLK_LSTM, 128, lstm_smem>>>(W_hh);
    {
        int n4 = M_ROWS * HID / 4;
        split_kernel<<<(n4 + 255) / 256, 256>>>((const float*)p_hall,
                                                (__nv_bfloat16*)p_hh, (__nv_bfloat16*)p_hl, n4);
    }
    gemm_vocab_mma_kernel<<<dim3(VOCAB/256, M_ROWS/128), 256, vg_smem>>>(bv, out);
}

// round 6
// speedup vs baseline: 1.9904x; 1.1336x over previous
#include <cuda_runtime.h>
#include <cuda_fp16.h>
#include <cuda_bf16.h>
#include <cstdint>
#include <cstddef>

#define VOCAB 32000
#define EMB   256
#define HID   512
#define FEAT  1024
#define BATCH 32
#define TT    100
#define M_ROWS (TT*BATCH)      // 3200
#define NBLK_LSTM 128
typedef unsigned long long ull;

// ---------------------------------------------------------------------------
// device scratch
// ---------------------------------------------------------------------------
__device__ float g_pooled[BATCH*FEAT];
__device__ float g_xg[(size_t)M_ROWS * 4 * HID];
__device__ float g_hall[(size_t)M_ROWS * HID];
__device__ float g_hping[2][BATCH*HID];
__device__ int   g_tok[M_ROWS];
__device__ unsigned g_barrier;

// fp16 buffers for the tensor-core vocab GEMM (asymmetric split)
__device__ __half g_wv_f16[(size_t)VOCAB * HID];   // single fp16 weights
__device__ __half g_h_hi[(size_t)M_ROWS * HID];    // h split hi
__device__ __half g_h_lo[(size_t)M_ROWS * HID];    // h split lo

// ---------------------------------------------------------------------------
// helpers
// ---------------------------------------------------------------------------
__device__ __forceinline__ uint32_t smem_u32(const void* p) {
    uint32_t a;
    asm("{ .reg .u64 t; cvta.to.shared.u64 t, %1; cvt.u32.u64 %0, t; }" : "=r"(a) : "l"(p));
    return a;
}
__device__ __forceinline__ void cp_async16(uint32_t dst, const void* src) {
    asm volatile("cp.async.cg.shared.global [%0], [%1], 16;" :: "r"(dst), "l"(src) : "memory");
}
#define CP_ASYNC_COMMIT() asm volatile("cp.async.commit_group;" ::: "memory")
#define CP_ASYNC_WAIT(n)  asm volatile("cp.async.wait_group %0;" :: "n"(n) : "memory")

__device__ __forceinline__ void ldsm_x4(uint32_t& r0, uint32_t& r1, uint32_t& r2, uint32_t& r3,
                                        uint32_t addr) {
    asm volatile("ldmatrix.sync.aligned.m8n8.x4.shared.b16 {%0,%1,%2,%3}, [%4];"
                 : "=r"(r0), "=r"(r1), "=r"(r2), "=r"(r3) : "r"(addr));
}
__device__ __forceinline__ void mma_f16(float* c, uint32_t a0, uint32_t a1, uint32_t a2, uint32_t a3,
                                        uint32_t b0, uint32_t b1) {
    asm volatile("mma.sync.aligned.m16n8k16.row.col.f32.f16.f16.f32 "
                 "{%0,%1,%2,%3}, {%4,%5,%6,%7}, {%8,%9}, {%0,%1,%2,%3};"
                 : "+f"(c[0]), "+f"(c[1]), "+f"(c[2]), "+f"(c[3])
                 : "r"(a0), "r"(a1), "r"(a2), "r"(a3), "r"(b0), "r"(b1));
}

__device__ __forceinline__ ull pack2(float x, float y) {
    ull r;
    asm("mov.b64 %0, {%1, %2};" : "=l"(r) : "r"(__float_as_uint(x)), "r"(__float_as_uint(y)));
    return r;
}
__device__ __forceinline__ void ffma2(ull& d, ull a, ull b) {
    asm("fma.rn.f32x2 %0, %1, %2, %3;" : "=l"(d) : "l"(a), "l"(b), "l"(d));
}
__device__ __forceinline__ float sum2(ull p) {
    return __uint_as_float((unsigned)p) + __uint_as_float((unsigned)(p >> 32));
}

// ---------------------------------------------------------------------------
// prep / pool / h0
// ---------------------------------------------------------------------------
__global__ void prep_kernel(const int* __restrict__ reports) {
    int i = blockIdx.x * blockDim.x + threadIdx.x;
    if (i == 0) g_barrier = 0u;
    if (i < M_ROWS) {
        int t = i >> 5, b = i & 31;
        g_tok[i] = (t == 0) ? 1 : reports[b * TT + (t - 1)];
    }
}

__global__ void pool_kernel(const float* __restrict__ feat) {
    int i = blockIdx.x * blockDim.x + threadIdx.x;
    if (i < BATCH * FEAT) {
        const float* p = feat + (size_t)i * 49;
        float s = 0.f;
        #pragma unroll
        for (int j = 0; j < 49; j++) s += p[j];
        g_pooled[i] = s * (1.f / 49.f);
    }
}

__global__ void h0_kernel(const float* __restrict__ fc_w, const float* __restrict__ fc_b) {
    int i = blockIdx.x * blockDim.x + threadIdx.x;
    if (i >= BATCH * HID) return;
    int b = i >> 9, j = i & 511;
    const float* pw = fc_w + (size_t)j * FEAT;
    const float* pp = g_pooled + (size_t)b * FEAT;
    float acc = fc_b[j];
    #pragma unroll 4
    for (int k = 0; k < FEAT; k++) acc = fmaf(pw[k], pp[k], acc);
    g_hping[0][b * HID + j] = acc;
}

// fp32 -> fp16 hi/lo split (A side)
__global__ void split_h_kernel(const float* __restrict__ src,
                               __half* __restrict__ hi,
                               __half* __restrict__ lo, int n4) {
    int i = blockIdx.x * blockDim.x + threadIdx.x;
    if (i >= n4) return;
    float4 v = reinterpret_cast<const float4*>(src)[i];
    float xs[4] = {v.x, v.y, v.z, v.w};
    __half h[4], l[4];
    #pragma unroll
    for (int j = 0; j < 4; j++) {
        h[j] = __float2half_rn(xs[j]);
        l[j] = __float2half_rn(xs[j] - __half2float(h[j]));
    }
    reinterpret_cast<__half2*>(hi)[i*2]   = __halves2half2(h[0], h[1]);
    reinterpret_cast<__half2*>(hi)[i*2+1] = __halves2half2(h[2], h[3]);
    reinterpret_cast<__half2*>(lo)[i*2]   = __halves2half2(l[0], l[1]);
    reinterpret_cast<__half2*>(lo)[i*2+1] = __halves2half2(l[2], l[3]);
}

// fp32 -> single fp16 (B side / weights)
__global__ void cvt_wv_kernel(const float* __restrict__ src, __half* __restrict__ dst, int n4) {
    int i = blockIdx.x * blockDim.x + threadIdx.x;
    if (i >= n4) return;
    float4 v = reinterpret_cast<const float4*>(src)[i];
    reinterpret_cast<__half2*>(dst)[i*2]   = __halves2half2(__float2half_rn(v.x), __float2half_rn(v.y));
    reinterpret_cast<__half2*>(dst)[i*2+1] = __halves2half2(__float2half_rn(v.z), __float2half_rn(v.w));
}

// ---------------------------------------------------------------------------
// SIMT fp32 GEMM (gates)
// ---------------------------------------------------------------------------
__global__ __launch_bounds__(256)
void gemm_gates_kernel(const float* __restrict__ Asrc, const float* __restrict__ Bsrc,
                       const float* __restrict__ bias0, const float* __restrict__ bias1,
                       float* __restrict__ C, int N, int K, const int* __restrict__ gidx)
{
    __shared__ float As[16 * 132];
    __shared__ float Bs[16 * 132];
    const int tid = threadIdx.x;
    const int n0 = blockIdx.x * 128;
    const int m0 = blockIdx.y * 128;
    const int ty = tid >> 4;
    const int tx = tid & 15;

    ull acc[8][4];
    #pragma unroll
    for (int i = 0; i < 8; i++)
        #pragma unroll
        for (int j = 0; j < 4; j++) acc[i][j] = 0ull;

    const int ml = tid >> 2;
    const int kq = (tid & 3) * 4;
    const float* arow0 = Asrc + (size_t)gidx[m0 + ml] * K;
    const float* arow1 = Asrc + (size_t)gidx[m0 + ml + 64] * K;
    const float* brow0 = Bsrc + (size_t)(n0 + ml) * K;
    const float* brow1 = Bsrc + (size_t)(n0 + ml + 64) * K;

    for (int k0 = 0; k0 < K; k0 += 16) {
        float4 a0  = *reinterpret_cast<const float4*>(arow0 + k0 + kq);
        float4 a1  = *reinterpret_cast<const float4*>(arow1 + k0 + kq);
        float4 bb0 = *reinterpret_cast<const float4*>(brow0 + k0 + kq);
        float4 bb1 = *reinterpret_cast<const float4*>(brow1 + k0 + kq);
        __syncthreads();
        As[(kq+0)*132 + ml] = a0.x;  As[(kq+1)*132 + ml] = a0.y;
        As[(kq+2)*132 + ml] = a0.z;  As[(kq+3)*132 + ml] = a0.w;
        As[(kq+0)*132 + ml+64] = a1.x;  As[(kq+1)*132 + ml+64] = a1.y;
        As[(kq+2)*132 + ml+64] = a1.z;  As[(kq+3)*132 + ml+64] = a1.w;
        Bs[(kq+0)*132 + ml] = bb0.x; Bs[(kq+1)*132 + ml] = bb0.y;
        Bs[(kq+2)*132 + ml] = bb0.z; Bs[(kq+3)*132 + ml] = bb0.w;
        Bs[(kq+0)*132 + ml+64] = bb1.x; Bs[(kq+1)*132 + ml+64] = bb1.y;
        Bs[(kq+2)*132 + ml+64] = bb1.z; Bs[(kq+3)*132 + ml+64] = bb1.w;
        __syncthreads();

        #pragma unroll
        for (int kk = 0; kk < 16; kk++) {
            const float* ar = As + kk*132 + ty*8;
            const float* br = Bs + kk*132 + tx*8;
            float4 av0 = *reinterpret_cast<const float4*>(ar);
            float4 av1 = *reinterpret_cast<const float4*>(ar + 4);
            float4 bv0 = *reinterpret_cast<const float4*>(br);
            float4 bv1 = *reinterpret_cast<const float4*>(br + 4);
            ull bp0 = pack2(bv0.x, bv0.y);
            ull bp1 = pack2(bv0.z, bv0.w);
            ull bp2 = pack2(bv1.x, bv1.y);
            ull bp3 = pack2(bv1.z, bv1.w);
            float aa[8] = {av0.x, av0.y, av0.z, av0.w, av1.x, av1.y, av1.z, av1.w};
            #pragma unroll
            for (int i = 0; i < 8; i++) {
                ull ap = pack2(aa[i], aa[i]);
                ffma2(acc[i][0], ap, bp0);
                ffma2(acc[i][1], ap, bp1);
                ffma2(acc[i][2], ap, bp2);
                ffma2(acc[i][3], ap, bp3);
            }
        }
    }

    float bias[8];
    #pragma unroll
    for (int j = 0; j < 8; j++) {
        int n = n0 + tx*8 + j;
        bias[j] = bias0[n] + bias1[n];
    }
    #pragma unroll
    for (int i = 0; i < 8; i++) {
        int m = m0 + ty*8 + i;
        size_t base = (size_t)m * (size_t)N + (size_t)(n0 + tx*8);
        float o[8];
        #pragma unroll
        for (int j = 0; j < 4; j++) {
            o[2*j]   = __uint_as_float((unsigned)(acc[i][j]))       + bias[2*j];
            o[2*j+1] = __uint_as_float((unsigned)(acc[i][j] >> 32)) + bias[2*j+1];
        }
        *reinterpret_cast<float4*>(C + base)     = make_float4(o[0], o[1], o[2], o[3]);
        *reinterpret_cast<float4*>(C + base + 4) = make_float4(o[4], o[5], o[6], o[7]);
    }
}

// ---------------------------------------------------------------------------
// grid barrier
// ---------------------------------------------------------------------------
__device__ __forceinline__ void grid_barrier(unsigned target) {
    __syncthreads();
    __threadfence();
    if (threadIdx.x == 0) {
        atomicAdd(&g_barrier, 1u);
        while (*((volatile unsigned*)&g_barrier) < target) { __nanosleep(64); }
    }
    __syncthreads();
    __threadfence();
}

// ---------------------------------------------------------------------------
// persistent LSTM recurrence (unchanged from R5)
// ---------------------------------------------------------------------------
#define WS_STRIDE 516
__global__ __launch_bounds__(128)
void lstm_kernel(const float* __restrict__ Whh) {
    extern __shared__ float sm[];
    float* ws  = sm;
    float* hs  = sm + 16*WS_STRIDE;
    float* gsm = sm + 16*WS_STRIDE + 32*WS_STRIDE;

    const int tid = threadIdx.x;
    const int n0  = blockIdx.x * 4;

    for (int lr = 0; lr < 16; lr++) {
        int u = lr >> 2, g = lr & 3;
        const float* src = Whh + (size_t)(g * HID + n0 + u) * HID;
        for (int k = tid; k < HID; k += 128) ws[lr * WS_STRIDE + k] = src[k];
    }

    const int rp = (tid & 1) + ((tid >> 5) << 1);
    const int r0 = rp * 2, r1 = r0 + 1;
    const int bp = (tid >> 1) & 15;
    const int b0 = bp * 2, b1 = b0 + 1;
    const int cu = tid >> 5;
    const int cb = tid & 31;
    float c_reg = 0.f;

    __syncthreads();

    for (int t = 0; t < TT; t++) {
        const float* hin = g_hping[t & 1];
        #pragma unroll 4
        for (int j = 0; j < 32; j++) {
            float4 v = __ldcg(reinterpret_cast<const float4*>(hin + j * HID + tid * 4));
            *reinterpret_cast<float4*>(hs + j * WS_STRIDE + tid * 4) = v;
        }
        __syncthreads();

        const ulonglong2* w0 = reinterpret_cast<const ulonglong2*>(ws + r0 * WS_STRIDE);
        const ulonglong2* w1 = reinterpret_cast<const ulonglong2*>(ws + r1 * WS_STRIDE);
        const ulonglong2* ha = reinterpret_cast<const ulonglong2*>(hs + b0 * WS_STRIDE);
        const ulonglong2* hb = reinterpret_cast<const ulonglong2*>(hs + b1 * WS_STRIDE);
        ull p00 = 0ull, p01 = 0ull, p10 = 0ull, p11 = 0ull;
        #pragma unroll 8
        for (int k = 0; k < HID/4; k++) {
            ulonglong2 wa = w0[k], wb = w1[k];
            ulonglong2 va = ha[k], vb = hb[k];
            ffma2(p00, wa.x, va.x); ffma2(p00, wa.y, va.y);
            ffma2(p01, wa.x, vb.x); ffma2(p01, wa.y, vb.y);
            ffma2(p10, wb.x, va.x); ffma2(p10, wb.y, va.y);
            ffma2(p11, wb.x, vb.x); ffma2(p11, wb.y, vb.y);
        }
        float a00 = sum2(p00), a01 = sum2(p01), a10 = sum2(p10), a11 = sum2(p11);
        {
            const size_t xt = (size_t)t * BATCH * (4*HID);
            int g0 = (r0 & 3) * HID + n0 + (r0 >> 2);
            int g1 = (r1 & 3) * HID + n0 + (r1 >> 2);
            gsm[r0*33 + b0] = a00 + g_xg[xt + (size_t)b0 * (4*HID) + g0];
            gsm[r0*33 + b1] = a01 + g_xg[xt + (size_t)b1 * (4*HID) + g0];
            gsm[r1*33 + b0] = a10 + g_xg[xt + (size_t)b0 * (4*HID) + g1];
            gsm[r1*33 + b1] = a11 + g_xg[xt + (size_t)b1 * (4*HID) + g1];
        }
        __syncthreads();

        {
            float iv = gsm[(cu*4 + 0)*33 + cb];
            float fv = gsm[(cu*4 + 1)*33 + cb];
            float gv = gsm[(cu*4 + 2)*33 + cb];
            float ov = gsm[(cu*4 + 3)*33 + cb];
            iv = 1.f / (1.f + __expf(-iv));
            fv = 1.f / (1.f + __expf(-fv));
            ov = 1.f / (1.f + __expf(-ov));
            gv = tanhf(gv);
            c_reg = fv * c_reg + iv * gv;
            float hn = ov * tanhf(c_reg);
            int nidx = n0 + cu;
            __stcg(&g_hping[(t + 1) & 1][cb * HID + nidx], hn);
            g_hall[((size_t)t * BATCH + cb) * HID + nidx] = hn;
        }
        grid_barrier((unsigned)((t + 1) * NBLK_LSTM));
    }
}

// ---------------------------------------------------------------------------
// Tensor-core vocab GEMM, fp16 asymmetric 2-product split:
//   D = Ahi*B + Alo*B,  A = h (fp16 hi+lo, 22-bit), B = Wv (single fp16)
// CTA tile 128x256, 8 warps (2x4), warp tile 64x64, K-chunk 64.
// Stage 64KB (Ahi 16K | Alo 16K | B 32K), 2 stages, cp.async pipeline.
// ---------------------------------------------------------------------------
#define VG_STAGE 65536

__global__ __launch_bounds__(256)
void gemm_vocab_mma_kernel(const float* __restrict__ bv, float* __restrict__ out)
{
    extern __shared__ char vsm[];
    const uint32_t smem = smem_u32(vsm);

    const int tid  = threadIdx.x;
    const int wid  = tid >> 5;
    const int lane = tid & 31;
    const int wm   = wid >> 2;          // 0..1  (64-row slabs)
    const int wn   = wid & 3;           // 0..3  (64-col slabs)
    const int n0   = blockIdx.x * 256;
    const int m0   = blockIdx.y * 128;

    float acc[4][8][4];
    #pragma unroll
    for (int i = 0; i < 4; i++)
        #pragma unroll
        for (int j = 0; j < 8; j++)
            #pragma unroll
            for (int q = 0; q < 4; q++) acc[i][j][q] = 0.f;

    // loader: 16 cp.async of 16B per thread per chunk (4096 total)
    auto load_chunk = [&](int chunk) {
        const uint32_t stage = smem + (uint32_t)(chunk & 1) * VG_STAGE;
        const int kbase = chunk * 64;
        #pragma unroll
        for (int j = 0; j < 16; j++) {
            int i = tid + j * 256;          // 0..4095
            const __half* gb;
            int grow;
            uint32_t doff;
            int cc;
            if (i < 2048) {                  // A: hi then lo (128 rows x 8 chunks each)
                int dt = i >> 10;
                int r  = (i >> 3) & 127;
                cc = i & 7;
                gb = dt ? g_h_lo : g_h_hi;
                grow = m0 + r;
                doff = (uint32_t)dt * 16384u + (uint32_t)(r * 128) + (uint32_t)(((cc ^ (r & 7)) * 16));
            } else {                         // B: 256 rows x 8 chunks
                int jj = i - 2048;
                int r  = (jj >> 3) & 255;
                cc = jj & 7;
                gb = g_wv_f16;
                grow = n0 + r;
                doff = 32768u + (uint32_t)(r * 128) + (uint32_t)(((cc ^ (r & 7)) * 16));
            }
            cp_async16(stage + doff, gb + (size_t)grow * HID + kbase + cc * 8);
        }
        CP_ASYNC_COMMIT();
    };

    load_chunk(0);

    for (int chunk = 0; chunk < 8; chunk++) {
        if (chunk + 1 < 8) { load_chunk(chunk + 1); CP_ASYNC_WAIT(1); }
        else               { CP_ASYNC_WAIT(0); }
        __syncthreads();

        const uint32_t stage = smem + (uint32_t)(chunk & 1) * VG_STAGE;
        const uint32_t aBase = stage;               // Ahi (Alo at +16384)
        const uint32_t bBase = stage + 32768u;      // B

        #pragma unroll
        for (int ks = 0; ks < 4; ks++) {
            // A fragments: 4 m-tiles x {hi,lo}
            uint32_t ah[4][4], al[4][4];
            #pragma unroll
            for (int mt = 0; mt < 4; mt++) {
                int row = wm * 64 + mt * 16 + (lane & 7) + ((lane >> 3) & 1) * 8;
                int ch  = ks * 2 + (lane >> 4);
                uint32_t off = (uint32_t)(row * 128) + (uint32_t)((ch ^ (row & 7)) * 16);
                ldsm_x4(ah[mt][0], ah[mt][1], ah[mt][2], ah[mt][3], aBase + off);
                ldsm_x4(al[mt][0], al[mt][1], al[mt][2], al[mt][3], aBase + 16384u + off);
            }
            // B: 4 groups of 16 cols
            #pragma unroll
            for (int p = 0; p < 4; p++) {
                int g   = lane >> 3;
                int row = wn * 64 + p * 16 + (g & 1) * 8 + (lane & 7);
                int ch  = ks * 2 + (g >> 1);
                uint32_t off = (uint32_t)(row * 128) + (uint32_t)((ch ^ (row & 7)) * 16);
                uint32_t bh[2][2];
                {
                    uint32_t r0, r1, r2, r3;
                    ldsm_x4(r0, r1, r2, r3, bBase + off);
                    bh[0][0] = r0; bh[0][1] = r2;
                    bh[1][0] = r1; bh[1][1] = r3;
                }
                #pragma unroll
                for (int mt = 0; mt < 4; mt++) {
                    #pragma unroll
                    for (int q = 0; q < 2; q++) {
                        int nt = p * 2 + q;
                        mma_f16(acc[mt][nt], ah[mt][0], ah[mt][1], ah[mt][2], ah[mt][3],
                                bh[q][0], bh[q][1]);
                        mma_f16(acc[mt][nt], al[mt][0], al[mt][1], al[mt][2], al[mt][3],
                                bh[q][0], bh[q][1]);
                    }
                }
            }
        }
        __syncthreads();
    }

    // epilogue: permuted rows, +bias, float2 stores
    #pragma unroll
    for (int mt = 0; mt < 4; mt++) {
        int gm0 = m0 + wm * 64 + mt * 16 + (lane >> 2);
        int gm1 = gm0 + 8;
        size_t ob0 = ((size_t)(gm0 & 31) * TT + (size_t)(gm0 >> 5)) * (size_t)VOCAB;
        size_t ob1 = ((size_t)(gm1 & 31) * TT + (size_t)(gm1 >> 5)) * (size_t)VOCAB;
        #pragma unroll
        for (int nt = 0; nt < 8; nt++) {
            int gn = n0 + wn * 64 + nt * 8 + (lane & 3) * 2;
            float bv0 = __ldg(bv + gn), bv1 = __ldg(bv + gn + 1);
            float2 v0 = make_float2(acc[mt][nt][0] + bv0, acc[mt][nt][1] + bv1);
            float2 v1 = make_float2(acc[mt][nt][2] + bv0, acc[mt][nt][3] + bv1);
            *reinterpret_cast<float2*>(out + ob0 + gn) = v0;
            *reinterpret_cast<float2*>(out + ob1 + gn) = v1;
        }
    }
}

// ---------------------------------------------------------------------------
// launch
// ---------------------------------------------------------------------------
extern "C" void kernel_launch(void* const* d_in, const int* in_sizes, int n_in,
                              void* d_out, int out_size) {
    const float* features  = (const float*)d_in[0];
    const int*   reports   = (const int*)  d_in[1];
    const float* emb_table = (const float*)d_in[2];
    const float* fc_w      = (const float*)d_in[3];
    const float* fc_b      = (const float*)d_in[4];
    const float* W_ih      = (const float*)d_in[5];
    const float* b_ih      = (const float*)d_in[6];
    const float* W_hh      = (const float*)d_in[7];
    const float* b_hh      = (const float*)d_in[8];
    const float* Wv        = (const float*)d_in[9];
    const float* bv        = (const float*)d_in[10];
    float* out = (float*)d_out;

    void *p_xg = nullptr, *p_hall = nullptr, *p_tok = nullptr;
    void *p_wv16 = nullptr, *p_hh = nullptr, *p_hl = nullptr;
    cudaGetSymbolAddress(&p_xg,   g_xg);
    cudaGetSymbolAddress(&p_hall, g_hall);
    cudaGetSymbolAddress(&p_tok,  g_tok);
    cudaGetSymbolAddress(&p_wv16, g_wv_f16);
    cudaGetSymbolAddress(&p_hh,   g_h_hi);
    cudaGetSymbolAddress(&p_hl,   g_h_lo);

    const int lstm_smem = (16*WS_STRIDE + 32*WS_STRIDE + 16*33) * (int)sizeof(float);
    cudaFuncSetAttribute(lstm_kernel, cudaFuncAttributeMaxDynamicSharedMemorySize, lstm_smem);
    const int vg_smem = 2 * VG_STAGE;   // 128 KB
    cudaFuncSetAttribute(gemm_vocab_mma_kernel, cudaFuncAttributeMaxDynamicSharedMemorySize, vg_smem);

    prep_kernel<<<(M_ROWS + 255) / 256, 256>>>(reports);
    pool_kernel<<<(BATCH * FEAT + 255) / 256, 256>>>(features);
    h0_kernel<<<(BATCH * HID + 255) / 256, 256>>>(fc_w, fc_b);
    {
        int n4 = VOCAB * HID / 4;
        cvt_wv_kernel<<<(n4 + 255) / 256, 256>>>(Wv, (__half*)p_wv16, n4);
    }
    gemm_gates_kernel<<<dim3(4*HID/128, M_ROWS/128), 256>>>(
        emb_table, W_ih, b_ih, b_hh, (float*)p_xg, 4*HID, EMB, (const int*)p_tok);
    lstm_kernel<<<NBLK_LSTM, 128, lstm_smem>>>(W_hh);
    {
        int n4 = M_ROWS * HID / 4;
        split_h_kernel<<<(n4 + 255) / 256, 256>>>((const float*)p_hall,
                                                  (__half*)p_hh, (__half*)p_hl, n4);
    }
    gemm_vocab_mma_kernel<<<dim3(VOCAB/256, M_ROWS/128), 256, vg_smem>>>(bv, out);
}

// round 7
// speedup vs baseline: 2.1353x; 1.0728x over previous
#include <cuda_runtime.h>
#include <cuda_fp16.h>
#include <cstdint>
#include <cstddef>

#define VOCAB 32000
#define EMB   256
#define HID   512
#define FEAT  1024
#define BATCH 32
#define TT    100
#define M_ROWS (TT*BATCH)      // 3200
#define NBLK_LSTM 128
typedef unsigned long long ull;

// ---------------------------------------------------------------------------
// device scratch
// ---------------------------------------------------------------------------
__device__ float g_pooled[BATCH*FEAT];
__device__ float g_xg[(size_t)M_ROWS * 4 * HID];
__device__ float g_hping[2][BATCH*HID];
__device__ int   g_tok[M_ROWS];
__device__ unsigned g_barrier;

// fp16 buffers for the tensor-core vocab GEMM (asymmetric split)
__device__ __half g_wv_f16[(size_t)VOCAB * HID];   // single fp16 weights
__device__ __half g_h_hi[(size_t)M_ROWS * HID];    // h split hi (written by LSTM)
__device__ __half g_h_lo[(size_t)M_ROWS * HID];    // h split lo (written by LSTM)

// ---------------------------------------------------------------------------
// helpers
// ---------------------------------------------------------------------------
__device__ __forceinline__ uint32_t smem_u32(const void* p) {
    uint32_t a;
    asm("{ .reg .u64 t; cvta.to.shared.u64 t, %1; cvt.u32.u64 %0, t; }" : "=r"(a) : "l"(p));
    return a;
}
__device__ __forceinline__ void cp_async16(uint32_t dst, const void* src) {
    asm volatile("cp.async.cg.shared.global [%0], [%1], 16;" :: "r"(dst), "l"(src) : "memory");
}
#define CP_ASYNC_COMMIT() asm volatile("cp.async.commit_group;" ::: "memory")
#define CP_ASYNC_WAIT(n)  asm volatile("cp.async.wait_group %0;" :: "n"(n) : "memory")

__device__ __forceinline__ void ldsm_x4(uint32_t& r0, uint32_t& r1, uint32_t& r2, uint32_t& r3,
                                        uint32_t addr) {
    asm volatile("ldmatrix.sync.aligned.m8n8.x4.shared.b16 {%0,%1,%2,%3}, [%4];"
                 : "=r"(r0), "=r"(r1), "=r"(r2), "=r"(r3) : "r"(addr));
}
__device__ __forceinline__ void mma_f16(float* c, uint32_t a0, uint32_t a1, uint32_t a2, uint32_t a3,
                                        uint32_t b0, uint32_t b1) {
    asm volatile("mma.sync.aligned.m16n8k16.row.col.f32.f16.f16.f32 "
                 "{%0,%1,%2,%3}, {%4,%5,%6,%7}, {%8,%9}, {%0,%1,%2,%3};"
                 : "+f"(c[0]), "+f"(c[1]), "+f"(c[2]), "+f"(c[3])
                 : "r"(a0), "r"(a1), "r"(a2), "r"(a3), "r"(b0), "r"(b1));
}

__device__ __forceinline__ ull pack2(float x, float y) {
    ull r;
    asm("mov.b64 %0, {%1, %2};" : "=l"(r) : "r"(__float_as_uint(x)), "r"(__float_as_uint(y)));
    return r;
}
__device__ __forceinline__ void ffma2(ull& d, ull a, ull b) {
    asm("fma.rn.f32x2 %0, %1, %2, %3;" : "=l"(d) : "l"(a), "l"(b), "l"(d));
}
__device__ __forceinline__ float sum2(ull p) {
    return __uint_as_float((unsigned)p) + __uint_as_float((unsigned)(p >> 32));
}

// ---------------------------------------------------------------------------
// prep / pool / h0 / weight convert
// ---------------------------------------------------------------------------
__global__ void prep_kernel(const int* __restrict__ reports) {
    int i = blockIdx.x * blockDim.x + threadIdx.x;
    if (i == 0) g_barrier = 0u;
    if (i < M_ROWS) {
        int t = i >> 5, b = i & 31;
        g_tok[i] = (t == 0) ? 1 : reports[b * TT + (t - 1)];
    }
}

__global__ void pool_kernel(const float* __restrict__ feat) {
    int i = blockIdx.x * blockDim.x + threadIdx.x;
    if (i < BATCH * FEAT) {
        const float* p = feat + (size_t)i * 49;
        float s = 0.f;
        #pragma unroll
        for (int j = 0; j < 49; j++) s += p[j];
        g_pooled[i] = s * (1.f / 49.f);
    }
}

__global__ void h0_kernel(const float* __restrict__ fc_w, const float* __restrict__ fc_b) {
    int i = blockIdx.x * blockDim.x + threadIdx.x;
    if (i >= BATCH * HID) return;
    int b = i >> 9, j = i & 511;
    const float* pw = fc_w + (size_t)j * FEAT;
    const float* pp = g_pooled + (size_t)b * FEAT;
    float acc = fc_b[j];
    #pragma unroll 4
    for (int k = 0; k < FEAT; k++) acc = fmaf(pw[k], pp[k], acc);
    g_hping[0][b * HID + j] = acc;
}

__global__ void cvt_wv_kernel(const float* __restrict__ src, __half* __restrict__ dst, int n4) {
    int i = blockIdx.x * blockDim.x + threadIdx.x;
    if (i >= n4) return;
    float4 v = reinterpret_cast<const float4*>(src)[i];
    reinterpret_cast<__half2*>(dst)[i*2]   = __halves2half2(__float2half_rn(v.x), __float2half_rn(v.y));
    reinterpret_cast<__half2*>(dst)[i*2+1] = __halves2half2(__float2half_rn(v.z), __float2half_rn(v.w));
}

// ---------------------------------------------------------------------------
// SIMT fp32 GEMM (gates)
// ---------------------------------------------------------------------------
__global__ __launch_bounds__(256)
void gemm_gates_kernel(const float* __restrict__ Asrc, const float* __restrict__ Bsrc,
                       const float* __restrict__ bias0, const float* __restrict__ bias1,
                       float* __restrict__ C, int N, int K, const int* __restrict__ gidx)
{
    __shared__ float As[16 * 132];
    __shared__ float Bs[16 * 132];
    const int tid = threadIdx.x;
    const int n0 = blockIdx.x * 128;
    const int m0 = blockIdx.y * 128;
    const int ty = tid >> 4;
    const int tx = tid & 15;

    ull acc[8][4];
    #pragma unroll
    for (int i = 0; i < 8; i++)
        #pragma unroll
        for (int j = 0; j < 4; j++) acc[i][j] = 0ull;

    const int ml = tid >> 2;
    const int kq = (tid & 3) * 4;
    const float* arow0 = Asrc + (size_t)gidx[m0 + ml] * K;
    const float* arow1 = Asrc + (size_t)gidx[m0 + ml + 64] * K;
    const float* brow0 = Bsrc + (size_t)(n0 + ml) * K;
    const float* brow1 = Bsrc + (size_t)(n0 + ml + 64) * K;

    for (int k0 = 0; k0 < K; k0 += 16) {
        float4 a0  = *reinterpret_cast<const float4*>(arow0 + k0 + kq);
        float4 a1  = *reinterpret_cast<const float4*>(arow1 + k0 + kq);
        float4 bb0 = *reinterpret_cast<const float4*>(brow0 + k0 + kq);
        float4 bb1 = *reinterpret_cast<const float4*>(brow1 + k0 + kq);
        __syncthreads();
        As[(kq+0)*132 + ml] = a0.x;  As[(kq+1)*132 + ml] = a0.y;
        As[(kq+2)*132 + ml] = a0.z;  As[(kq+3)*132 + ml] = a0.w;
        As[(kq+0)*132 + ml+64] = a1.x;  As[(kq+1)*132 + ml+64] = a1.y;
        As[(kq+2)*132 + ml+64] = a1.z;  As[(kq+3)*132 + ml+64] = a1.w;
        Bs[(kq+0)*132 + ml] = bb0.x; Bs[(kq+1)*132 + ml] = bb0.y;
        Bs[(kq+2)*132 + ml] = bb0.z; Bs[(kq+3)*132 + ml] = bb0.w;
        Bs[(kq+0)*132 + ml+64] = bb1.x; Bs[(kq+1)*132 + ml+64] = bb1.y;
        Bs[(kq+2)*132 + ml+64] = bb1.z; Bs[(kq+3)*132 + ml+64] = bb1.w;
        __syncthreads();

        #pragma unroll
        for (int kk = 0; kk < 16; kk++) {
            const float* ar = As + kk*132 + ty*8;
            const float* br = Bs + kk*132 + tx*8;
            float4 av0 = *reinterpret_cast<const float4*>(ar);
            float4 av1 = *reinterpret_cast<const float4*>(ar + 4);
            float4 bv0 = *reinterpret_cast<const float4*>(br);
            float4 bv1 = *reinterpret_cast<const float4*>(br + 4);
            ull bp0 = pack2(bv0.x, bv0.y);
            ull bp1 = pack2(bv0.z, bv0.w);
            ull bp2 = pack2(bv1.x, bv1.y);
            ull bp3 = pack2(bv1.z, bv1.w);
            float aa[8] = {av0.x, av0.y, av0.z, av0.w, av1.x, av1.y, av1.z, av1.w};
            #pragma unroll
            for (int i = 0; i < 8; i++) {
                ull ap = pack2(aa[i], aa[i]);
                ffma2(acc[i][0], ap, bp0);
                ffma2(acc[i][1], ap, bp1);
                ffma2(acc[i][2], ap, bp2);
                ffma2(acc[i][3], ap, bp3);
            }
        }
    }

    float bias[8];
    #pragma unroll
    for (int j = 0; j < 8; j++) {
        int n = n0 + tx*8 + j;
        bias[j] = bias0[n] + bias1[n];
    }
    #pragma unroll
    for (int i = 0; i < 8; i++) {
        int m = m0 + ty*8 + i;
        size_t base = (size_t)m * (size_t)N + (size_t)(n0 + tx*8);
        float o[8];
        #pragma unroll
        for (int j = 0; j < 4; j++) {
            o[2*j]   = __uint_as_float((unsigned)(acc[i][j]))       + bias[2*j];
            o[2*j+1] = __uint_as_float((unsigned)(acc[i][j] >> 32)) + bias[2*j+1];
        }
        *reinterpret_cast<float4*>(C + base)     = make_float4(o[0], o[1], o[2], o[3]);
        *reinterpret_cast<float4*>(C + base + 4) = make_float4(o[4], o[5], o[6], o[7]);
    }
}

// ---------------------------------------------------------------------------
// grid barrier
// ---------------------------------------------------------------------------
__device__ __forceinline__ void grid_barrier(unsigned target) {
    __syncthreads();
    __threadfence();
    if (threadIdx.x == 0) {
        atomicAdd(&g_barrier, 1u);
        while (*((volatile unsigned*)&g_barrier) < target) { __nanosleep(64); }
    }
    __syncthreads();
    __threadfence();
}

// ---------------------------------------------------------------------------
// persistent LSTM recurrence.
// R7: xg prefetch at step start (hides DRAM latency behind phases A+B);
//     phase C writes h directly as fp16 hi/lo (split kernel deleted);
//     last grid barrier skipped.
// ---------------------------------------------------------------------------
#define WS_STRIDE 516
__global__ __launch_bounds__(128)
void lstm_kernel(const float* __restrict__ Whh) {
    extern __shared__ float sm[];
    float* ws  = sm;
    float* hs  = sm + 16*WS_STRIDE;
    float* gsm = sm + 16*WS_STRIDE + 32*WS_STRIDE;

    const int tid = threadIdx.x;
    const int n0  = blockIdx.x * 4;

    for (int lr = 0; lr < 16; lr++) {
        int u = lr >> 2, g = lr & 3;
        const float* src = Whh + (size_t)(g * HID + n0 + u) * HID;
        for (int k = tid; k < HID; k += 128) ws[lr * WS_STRIDE + k] = src[k];
    }

    const int rp = (tid & 1) + ((tid >> 5) << 1);
    const int r0 = rp * 2, r1 = r0 + 1;
    const int bp = (tid >> 1) & 15;
    const int b0 = bp * 2, b1 = b0 + 1;
    const int cu = tid >> 5;
    const int cb = tid & 31;
    const int g0 = (r0 & 3) * HID + n0 + (r0 >> 2);
    const int g1 = (r1 & 3) * HID + n0 + (r1 >> 2);
    float c_reg = 0.f;

    __syncthreads();

    for (int t = 0; t < TT; t++) {
        // xg prefetch (DRAM latency overlaps phases A+B)
        const size_t xt = (size_t)t * BATCH * (4*HID);
        float x00 = __ldcg(&g_xg[xt + (size_t)b0 * (4*HID) + g0]);
        float x01 = __ldcg(&g_xg[xt + (size_t)b1 * (4*HID) + g0]);
        float x10 = __ldcg(&g_xg[xt + (size_t)b0 * (4*HID) + g1]);
        float x11 = __ldcg(&g_xg[xt + (size_t)b1 * (4*HID) + g1]);

        // phase A: h(ping) -> hs
        const float* hin = g_hping[t & 1];
        #pragma unroll 4
        for (int j = 0; j < 32; j++) {
            float4 v = __ldcg(reinterpret_cast<const float4*>(hin + j * HID + tid * 4));
            *reinterpret_cast<float4*>(hs + j * WS_STRIDE + tid * 4) = v;
        }
        __syncthreads();

        // phase B
        const ulonglong2* w0 = reinterpret_cast<const ulonglong2*>(ws + r0 * WS_STRIDE);
        const ulonglong2* w1 = reinterpret_cast<const ulonglong2*>(ws + r1 * WS_STRIDE);
        const ulonglong2* ha = reinterpret_cast<const ulonglong2*>(hs + b0 * WS_STRIDE);
        const ulonglong2* hb = reinterpret_cast<const ulonglong2*>(hs + b1 * WS_STRIDE);
        ull p00 = 0ull, p01 = 0ull, p10 = 0ull, p11 = 0ull;
        #pragma unroll 8
        for (int k = 0; k < HID/4; k++) {
            ulonglong2 wa = w0[k], wb = w1[k];
            ulonglong2 va = ha[k], vb = hb[k];
            ffma2(p00, wa.x, va.x); ffma2(p00, wa.y, va.y);
            ffma2(p01, wa.x, vb.x); ffma2(p01, wa.y, vb.y);
            ffma2(p10, wb.x, va.x); ffma2(p10, wb.y, va.y);
            ffma2(p11, wb.x, vb.x); ffma2(p11, wb.y, vb.y);
        }
        gsm[r0*33 + b0] = sum2(p00) + x00;
        gsm[r0*33 + b1] = sum2(p01) + x01;
        gsm[r1*33 + b0] = sum2(p10) + x10;
        gsm[r1*33 + b1] = sum2(p11) + x11;
        __syncthreads();

        // phase C
        {
            float iv = gsm[(cu*4 + 0)*33 + cb];
            float fv = gsm[(cu*4 + 1)*33 + cb];
            float gv = gsm[(cu*4 + 2)*33 + cb];
            float ov = gsm[(cu*4 + 3)*33 + cb];
            iv = 1.f / (1.f + __expf(-iv));
            fv = 1.f / (1.f + __expf(-fv));
            ov = 1.f / (1.f + __expf(-ov));
            gv = tanhf(gv);
            c_reg = fv * c_reg + iv * gv;
            float hn = ov * tanhf(c_reg);
            int nidx = n0 + cu;
            __stcg(&g_hping[(t + 1) & 1][cb * HID + nidx], hn);
            // write fp16 hi/lo split directly (row m = t*32 + cb)
            __half hh = __float2half_rn(hn);
            __half hl = __float2half_rn(hn - __half2float(hh));
            size_t hrow = ((size_t)t * BATCH + cb) * HID + nidx;
            g_h_hi[hrow] = hh;
            g_h_lo[hrow] = hl;
        }
        if (t + 1 < TT) grid_barrier((unsigned)((t + 1) * NBLK_LSTM));
    }
}

// ---------------------------------------------------------------------------
// Tensor-core vocab GEMM, fp16 asymmetric 2-product split:
//   D = Ahi*B + Alo*B
// R7: 512 threads / 16 warps (4 per SMSP), warp tile 32x64; CTA tile 128x256,
// K-chunk 64, stage 64KB (Ahi 16K | Alo 16K | B 32K), 2 stages.
// ---------------------------------------------------------------------------
#define VG_STAGE 65536

__global__ __launch_bounds__(512)
void gemm_vocab_mma_kernel(const float* __restrict__ bv, float* __restrict__ out)
{
    extern __shared__ char vsm[];
    const uint32_t smem = smem_u32(vsm);

    const int tid  = threadIdx.x;
    const int wid  = tid >> 5;
    const int lane = tid & 31;
    const int wm   = wid >> 2;          // 0..3  (32-row slabs)
    const int wn   = wid & 3;           // 0..3  (64-col slabs)
    const int n0   = blockIdx.x * 256;
    const int m0   = blockIdx.y * 128;

    float acc[2][8][4];
    #pragma unroll
    for (int i = 0; i < 2; i++)
        #pragma unroll
        for (int j = 0; j < 8; j++)
            #pragma unroll
            for (int q = 0; q < 4; q++) acc[i][j][q] = 0.f;

    // loader: 8 cp.async of 16B per thread per chunk (4096 total)
    auto load_chunk = [&](int chunk) {
        const uint32_t stage = smem + (uint32_t)(chunk & 1) * VG_STAGE;
        const int kbase = chunk * 64;
        #pragma unroll
        for (int j = 0; j < 8; j++) {
            int i = tid + j * 512;          // 0..4095
            const __half* gb;
            int grow;
            uint32_t doff;
            int cc;
            if (i < 2048) {                  // A: hi then lo
                int dt = i >> 10;
                int r  = (i >> 3) & 127;
                cc = i & 7;
                gb = dt ? g_h_lo : g_h_hi;
                grow = m0 + r;
                doff = (uint32_t)dt * 16384u + (uint32_t)(r * 128) + (uint32_t)(((cc ^ (r & 7)) * 16));
            } else {                         // B
                int jj = i - 2048;
                int r  = (jj >> 3) & 255;
                cc = jj & 7;
                gb = g_wv_f16;
                grow = n0 + r;
                doff = 32768u + (uint32_t)(r * 128) + (uint32_t)(((cc ^ (r & 7)) * 16));
            }
            cp_async16(stage + doff, gb + (size_t)grow * HID + kbase + cc * 8);
        }
        CP_ASYNC_COMMIT();
    };

    load_chunk(0);

    for (int chunk = 0; chunk < 8; chunk++) {
        if (chunk + 1 < 8) { load_chunk(chunk + 1); CP_ASYNC_WAIT(1); }
        else               { CP_ASYNC_WAIT(0); }
        __syncthreads();

        const uint32_t stage = smem + (uint32_t)(chunk & 1) * VG_STAGE;
        const uint32_t aBase = stage;               // Ahi (Alo at +16384)
        const uint32_t bBase = stage + 32768u;      // B

        #pragma unroll
        for (int ks = 0; ks < 4; ks++) {
            // A fragments: 2 m-tiles x {hi,lo}
            uint32_t ah[2][4], al[2][4];
            #pragma unroll
            for (int mt = 0; mt < 2; mt++) {
                int row = wm * 32 + mt * 16 + (lane & 7) + ((lane >> 3) & 1) * 8;
                int ch  = ks * 2 + (lane >> 4);
                uint32_t off = (uint32_t)(row * 128) + (uint32_t)((ch ^ (row & 7)) * 16);
                ldsm_x4(ah[mt][0], ah[mt][1], ah[mt][2], ah[mt][3], aBase + off);
                ldsm_x4(al[mt][0], al[mt][1], al[mt][2], al[mt][3], aBase + 16384u + off);
            }
            // B: 4 groups of 16 cols
            #pragma unroll
            for (int p = 0; p < 4; p++) {
                int g   = lane >> 3;
                int row = wn * 64 + p * 16 + (g & 1) * 8 + (lane & 7);
                int ch  = ks * 2 + (g >> 1);
                uint32_t off = (uint32_t)(row * 128) + (uint32_t)((ch ^ (row & 7)) * 16);
                uint32_t bh[2][2];
                {
                    uint32_t r0, r1, r2, r3;
                    ldsm_x4(r0, r1, r2, r3, bBase + off);
                    bh[0][0] = r0; bh[0][1] = r2;
                    bh[1][0] = r1; bh[1][1] = r3;
                }
                #pragma unroll
                for (int mt = 0; mt < 2; mt++) {
                    #pragma unroll
                    for (int q = 0; q < 2; q++) {
                        int nt = p * 2 + q;
                        mma_f16(acc[mt][nt], ah[mt][0], ah[mt][1], ah[mt][2], ah[mt][3],
                                bh[q][0], bh[q][1]);
                        mma_f16(acc[mt][nt], al[mt][0], al[mt][1], al[mt][2], al[mt][3],
                                bh[q][0], bh[q][1]);
                    }
                }
            }
        }
        __syncthreads();
    }

    // epilogue: permuted rows, +bias, float2 stores
    #pragma unroll
    for (int mt = 0; mt < 2; mt++) {
        int gm0 = m0 + wm * 32 + mt * 16 + (lane >> 2);
        int gm1 = gm0 + 8;
        size_t ob0 = ((size_t)(gm0 & 31) * TT + (size_t)(gm0 >> 5)) * (size_t)VOCAB;
        size_t ob1 = ((size_t)(gm1 & 31) * TT + (size_t)(gm1 >> 5)) * (size_t)VOCAB;
        #pragma unroll
        for (int nt = 0; nt < 8; nt++) {
            int gn = n0 + wn * 64 + nt * 8 + (lane & 3) * 2;
            float bv0 = __ldg(bv + gn), bv1 = __ldg(bv + gn + 1);
            float2 v0 = make_float2(acc[mt][nt][0] + bv0, acc[mt][nt][1] + bv1);
            float2 v1 = make_float2(acc[mt][nt][2] + bv0, acc[mt][nt][3] + bv1);
            *reinterpret_cast<float2*>(out + ob0 + gn) = v0;
            *reinterpret_cast<float2*>(out + ob1 + gn) = v1;
        }
    }
}

// ---------------------------------------------------------------------------
// launch
// ---------------------------------------------------------------------------
extern "C" void kernel_launch(void* const* d_in, const int* in_sizes, int n_in,
                              void* d_out, int out_size) {
    const float* features  = (const float*)d_in[0];
    const int*   reports   = (const int*)  d_in[1];
    const float* emb_table = (const float*)d_in[2];
    const float* fc_w      = (const float*)d_in[3];
    const float* fc_b      = (const float*)d_in[4];
    const float* W_ih      = (const float*)d_in[5];
    const float* b_ih      = (const float*)d_in[6];
    const float* W_hh      = (const float*)d_in[7];
    const float* b_hh      = (const float*)d_in[8];
    const float* Wv        = (const float*)d_in[9];
    const float* bv        = (const float*)d_in[10];
    float* out = (float*)d_out;

    void *p_xg = nullptr, *p_tok = nullptr, *p_wv16 = nullptr;
    cudaGetSymbolAddress(&p_xg,   g_xg);
    cudaGetSymbolAddress(&p_tok,  g_tok);
    cudaGetSymbolAddress(&p_wv16, g_wv_f16);

    const int lstm_smem = (16*WS_STRIDE + 32*WS_STRIDE + 16*33) * (int)sizeof(float);
    cudaFuncSetAttribute(lstm_kernel, cudaFuncAttributeMaxDynamicSharedMemorySize, lstm_smem);
    const int vg_smem = 2 * VG_STAGE;   // 128 KB
    cudaFuncSetAttribute(gemm_vocab_mma_kernel, cudaFuncAttributeMaxDynamicSharedMemorySize, vg_smem);

    prep_kernel<<<(M_ROWS + 255) / 256, 256>>>(reports);
    pool_kernel<<<(BATCH * FEAT + 255) / 256, 256>>>(features);
    h0_kernel<<<(BATCH * HID + 255) / 256, 256>>>(fc_w, fc_b);
    {
        int n4 = VOCAB * HID / 4;
        cvt_wv_kernel<<<(n4 + 255) / 256, 256>>>(Wv, (__half*)p_wv16, n4);
    }
    gemm_gates_kernel<<<dim3(4*HID/128, M_ROWS/128), 256>>>(
        emb_table, W_ih, b_ih, b_hh, (float*)p_xg, 4*HID, EMB, (const int*)p_tok);
    lstm_kernel<<<NBLK_LSTM, 128, lstm_smem>>>(W_hh);
    gemm_vocab_mma_kernel<<<dim3(VOCAB/256, M_ROWS/128), 512, vg_smem>>>(bv, out);
}

// round 8
// speedup vs baseline: 2.4168x; 1.1318x over previous
#include <cuda_runtime.h>
#include <cuda_fp16.h>
#include <cstdint>
#include <cstddef>

#define VOCAB 32000
#define EMB   256
#define HID   512
#define FEAT  1024
#define BATCH 32
#define TT    100
#define M_ROWS (TT*BATCH)      // 3200
#define NBLK_LSTM 128
typedef unsigned long long ull;

// ---------------------------------------------------------------------------
// device scratch
// ---------------------------------------------------------------------------
__device__ float g_pooled[BATCH*FEAT];
__device__ float g_xg[(size_t)M_ROWS * 4 * HID];
__device__ float g_hping[2][BATCH*HID];
__device__ int   g_tok[M_ROWS];
__device__ unsigned g_barrier;

// fp16 buffers for the tensor-core vocab GEMM
__device__ __half g_wv_f16[(size_t)VOCAB * HID];   // fp16 weights
__device__ __half g_h_f16[(size_t)M_ROWS * HID];   // fp16 h (written by LSTM)

// ---------------------------------------------------------------------------
// helpers
// ---------------------------------------------------------------------------
__device__ __forceinline__ uint32_t smem_u32(const void* p) {
    uint32_t a;
    asm("{ .reg .u64 t; cvta.to.shared.u64 t, %1; cvt.u32.u64 %0, t; }" : "=r"(a) : "l"(p));
    return a;
}
__device__ __forceinline__ void cp_async16(uint32_t dst, const void* src) {
    asm volatile("cp.async.cg.shared.global [%0], [%1], 16;" :: "r"(dst), "l"(src) : "memory");
}
#define CP_ASYNC_COMMIT() asm volatile("cp.async.commit_group;" ::: "memory")
#define CP_ASYNC_WAIT(n)  asm volatile("cp.async.wait_group %0;" :: "n"(n) : "memory")

__device__ __forceinline__ void ldsm_x4(uint32_t& r0, uint32_t& r1, uint32_t& r2, uint32_t& r3,
                                        uint32_t addr) {
    asm volatile("ldmatrix.sync.aligned.m8n8.x4.shared.b16 {%0,%1,%2,%3}, [%4];"
                 : "=r"(r0), "=r"(r1), "=r"(r2), "=r"(r3) : "r"(addr));
}
__device__ __forceinline__ void mma_f16(float* c, uint32_t a0, uint32_t a1, uint32_t a2, uint32_t a3,
                                        uint32_t b0, uint32_t b1) {
    asm volatile("mma.sync.aligned.m16n8k16.row.col.f32.f16.f16.f32 "
                 "{%0,%1,%2,%3}, {%4,%5,%6,%7}, {%8,%9}, {%0,%1,%2,%3};"
                 : "+f"(c[0]), "+f"(c[1]), "+f"(c[2]), "+f"(c[3])
                 : "r"(a0), "r"(a1), "r"(a2), "r"(a3), "r"(b0), "r"(b1));
}

__device__ __forceinline__ ull pack2(float x, float y) {
    ull r;
    asm("mov.b64 %0, {%1, %2};" : "=l"(r) : "r"(__float_as_uint(x)), "r"(__float_as_uint(y)));
    return r;
}
__device__ __forceinline__ void ffma2(ull& d, ull a, ull b) {
    asm("fma.rn.f32x2 %0, %1, %2, %3;" : "=l"(d) : "l"(a), "l"(b), "l"(d));
}
__device__ __forceinline__ float sum2(ull p) {
    return __uint_as_float((unsigned)p) + __uint_as_float((unsigned)(p >> 32));
}

// ---------------------------------------------------------------------------
// prep / pool / h0 / weight convert
// ---------------------------------------------------------------------------
__global__ void prep_kernel(const int* __restrict__ reports) {
    int i = blockIdx.x * blockDim.x + threadIdx.x;
    if (i == 0) g_barrier = 0u;
    if (i < M_ROWS) {
        int t = i >> 5, b = i & 31;
        g_tok[i] = (t == 0) ? 1 : reports[b * TT + (t - 1)];
    }
}

__global__ void pool_kernel(const float* __restrict__ feat) {
    int i = blockIdx.x * blockDim.x + threadIdx.x;
    if (i < BATCH * FEAT) {
        const float* p = feat + (size_t)i * 49;
        float s = 0.f;
        #pragma unroll
        for (int j = 0; j < 49; j++) s += p[j];
        g_pooled[i] = s * (1.f / 49.f);
    }
}

__global__ void h0_kernel(const float* __restrict__ fc_w, const float* __restrict__ fc_b) {
    int i = blockIdx.x * blockDim.x + threadIdx.x;
    if (i >= BATCH * HID) return;
    int b = i >> 9, j = i & 511;
    const float* pw = fc_w + (size_t)j * FEAT;
    const float* pp = g_pooled + (size_t)b * FEAT;
    float acc = fc_b[j];
    #pragma unroll 4
    for (int k = 0; k < FEAT; k++) acc = fmaf(pw[k], pp[k], acc);
    g_hping[0][b * HID + j] = acc;
}

__global__ void cvt_wv_kernel(const float* __restrict__ src, __half* __restrict__ dst, int n4) {
    int i = blockIdx.x * blockDim.x + threadIdx.x;
    if (i >= n4) return;
    float4 v = reinterpret_cast<const float4*>(src)[i];
    reinterpret_cast<__half2*>(dst)[i*2]   = __halves2half2(__float2half_rn(v.x), __float2half_rn(v.y));
    reinterpret_cast<__half2*>(dst)[i*2+1] = __halves2half2(__float2half_rn(v.z), __float2half_rn(v.w));
}

// ---------------------------------------------------------------------------
// SIMT fp32 GEMM (gates)
// ---------------------------------------------------------------------------
__global__ __launch_bounds__(256)
void gemm_gates_kernel(const float* __restrict__ Asrc, const float* __restrict__ Bsrc,
                       const float* __restrict__ bias0, const float* __restrict__ bias1,
                       float* __restrict__ C, int N, int K, const int* __restrict__ gidx)
{
    __shared__ float As[16 * 132];
    __shared__ float Bs[16 * 132];
    const int tid = threadIdx.x;
    const int n0 = blockIdx.x * 128;
    const int m0 = blockIdx.y * 128;
    const int ty = tid >> 4;
    const int tx = tid & 15;

    ull acc[8][4];
    #pragma unroll
    for (int i = 0; i < 8; i++)
        #pragma unroll
        for (int j = 0; j < 4; j++) acc[i][j] = 0ull;

    const int ml = tid >> 2;
    const int kq = (tid & 3) * 4;
    const float* arow0 = Asrc + (size_t)gidx[m0 + ml] * K;
    const float* arow1 = Asrc + (size_t)gidx[m0 + ml + 64] * K;
    const float* brow0 = Bsrc + (size_t)(n0 + ml) * K;
    const float* brow1 = Bsrc + (size_t)(n0 + ml + 64) * K;

    for (int k0 = 0; k0 < K; k0 += 16) {
        float4 a0  = *reinterpret_cast<const float4*>(arow0 + k0 + kq);
        float4 a1  = *reinterpret_cast<const float4*>(arow1 + k0 + kq);
        float4 bb0 = *reinterpret_cast<const float4*>(brow0 + k0 + kq);
        float4 bb1 = *reinterpret_cast<const float4*>(brow1 + k0 + kq);
        __syncthreads();
        As[(kq+0)*132 + ml] = a0.x;  As[(kq+1)*132 + ml] = a0.y;
        As[(kq+2)*132 + ml] = a0.z;  As[(kq+3)*132 + ml] = a0.w;
        As[(kq+0)*132 + ml+64] = a1.x;  As[(kq+1)*132 + ml+64] = a1.y;
        As[(kq+2)*132 + ml+64] = a1.z;  As[(kq+3)*132 + ml+64] = a1.w;
        Bs[(kq+0)*132 + ml] = bb0.x; Bs[(kq+1)*132 + ml] = bb0.y;
        Bs[(kq+2)*132 + ml] = bb0.z; Bs[(kq+3)*132 + ml] = bb0.w;
        Bs[(kq+0)*132 + ml+64] = bb1.x; Bs[(kq+1)*132 + ml+64] = bb1.y;
        Bs[(kq+2)*132 + ml+64] = bb1.z; Bs[(kq+3)*132 + ml+64] = bb1.w;
        __syncthreads();

        #pragma unroll
        for (int kk = 0; kk < 16; kk++) {
            const float* ar = As + kk*132 + ty*8;
            const float* br = Bs + kk*132 + tx*8;
            float4 av0 = *reinterpret_cast<const float4*>(ar);
            float4 av1 = *reinterpret_cast<const float4*>(ar + 4);
            float4 bv0 = *reinterpret_cast<const float4*>(br);
            float4 bv1 = *reinterpret_cast<const float4*>(br + 4);
            ull bp0 = pack2(bv0.x, bv0.y);
            ull bp1 = pack2(bv0.z, bv0.w);
            ull bp2 = pack2(bv1.x, bv1.y);
            ull bp3 = pack2(bv1.z, bv1.w);
            float aa[8] = {av0.x, av0.y, av0.z, av0.w, av1.x, av1.y, av1.z, av1.w};
            #pragma unroll
            for (int i = 0; i < 8; i++) {
                ull ap = pack2(aa[i], aa[i]);
                ffma2(acc[i][0], ap, bp0);
                ffma2(acc[i][1], ap, bp1);
                ffma2(acc[i][2], ap, bp2);
                ffma2(acc[i][3], ap, bp3);
            }
        }
    }

    float bias[8];
    #pragma unroll
    for (int j = 0; j < 8; j++) {
        int n = n0 + tx*8 + j;
        bias[j] = bias0[n] + bias1[n];
    }
    #pragma unroll
    for (int i = 0; i < 8; i++) {
        int m = m0 + ty*8 + i;
        size_t base = (size_t)m * (size_t)N + (size_t)(n0 + tx*8);
        float o[8];
        #pragma unroll
        for (int j = 0; j < 4; j++) {
            o[2*j]   = __uint_as_float((unsigned)(acc[i][j]))       + bias[2*j];
            o[2*j+1] = __uint_as_float((unsigned)(acc[i][j] >> 32)) + bias[2*j+1];
        }
        *reinterpret_cast<float4*>(C + base)     = make_float4(o[0], o[1], o[2], o[3]);
        *reinterpret_cast<float4*>(C + base + 4) = make_float4(o[4], o[5], o[6], o[7]);
    }
}

// ---------------------------------------------------------------------------
// grid barrier
// ---------------------------------------------------------------------------
__device__ __forceinline__ void grid_barrier(unsigned target) {
    __syncthreads();
    __threadfence();
    if (threadIdx.x == 0) {
        atomicAdd(&g_barrier, 1u);
        while (*((volatile unsigned*)&g_barrier) < target) { __nanosleep(64); }
    }
    __syncthreads();
    __threadfence();
}

// ---------------------------------------------------------------------------
// persistent LSTM recurrence (R7 structure; h written as single fp16)
// ---------------------------------------------------------------------------
#define WS_STRIDE 516
__global__ __launch_bounds__(128)
void lstm_kernel(const float* __restrict__ Whh) {
    extern __shared__ float sm[];
    float* ws  = sm;
    float* hs  = sm + 16*WS_STRIDE;
    float* gsm = sm + 16*WS_STRIDE + 32*WS_STRIDE;

    const int tid = threadIdx.x;
    const int n0  = blockIdx.x * 4;

    for (int lr = 0; lr < 16; lr++) {
        int u = lr >> 2, g = lr & 3;
        const float* src = Whh + (size_t)(g * HID + n0 + u) * HID;
        for (int k = tid; k < HID; k += 128) ws[lr * WS_STRIDE + k] = src[k];
    }

    const int rp = (tid & 1) + ((tid >> 5) << 1);
    const int r0 = rp * 2, r1 = r0 + 1;
    const int bp = (tid >> 1) & 15;
    const int b0 = bp * 2, b1 = b0 + 1;
    const int cu = tid >> 5;
    const int cb = tid & 31;
    const int g0 = (r0 & 3) * HID + n0 + (r0 >> 2);
    const int g1 = (r1 & 3) * HID + n0 + (r1 >> 2);
    float c_reg = 0.f;

    __syncthreads();

    for (int t = 0; t < TT; t++) {
        // xg prefetch (DRAM latency overlaps phases A+B)
        const size_t xt = (size_t)t * BATCH * (4*HID);
        float x00 = __ldcg(&g_xg[xt + (size_t)b0 * (4*HID) + g0]);
        float x01 = __ldcg(&g_xg[xt + (size_t)b1 * (4*HID) + g0]);
        float x10 = __ldcg(&g_xg[xt + (size_t)b0 * (4*HID) + g1]);
        float x11 = __ldcg(&g_xg[xt + (size_t)b1 * (4*HID) + g1]);

        // phase A: h(ping) -> hs
        const float* hin = g_hping[t & 1];
        #pragma unroll 4
        for (int j = 0; j < 32; j++) {
            float4 v = __ldcg(reinterpret_cast<const float4*>(hin + j * HID + tid * 4));
            *reinterpret_cast<float4*>(hs + j * WS_STRIDE + tid * 4) = v;
        }
        __syncthreads();

        // phase B
        const ulonglong2* w0 = reinterpret_cast<const ulonglong2*>(ws + r0 * WS_STRIDE);
        const ulonglong2* w1 = reinterpret_cast<const ulonglong2*>(ws + r1 * WS_STRIDE);
        const ulonglong2* ha = reinterpret_cast<const ulonglong2*>(hs + b0 * WS_STRIDE);
        const ulonglong2* hb = reinterpret_cast<const ulonglong2*>(hs + b1 * WS_STRIDE);
        ull p00 = 0ull, p01 = 0ull, p10 = 0ull, p11 = 0ull;
        #pragma unroll 8
        for (int k = 0; k < HID/4; k++) {
            ulonglong2 wa = w0[k], wb = w1[k];
            ulonglong2 va = ha[k], vb = hb[k];
            ffma2(p00, wa.x, va.x); ffma2(p00, wa.y, va.y);
            ffma2(p01, wa.x, vb.x); ffma2(p01, wa.y, vb.y);
            ffma2(p10, wb.x, va.x); ffma2(p10, wb.y, va.y);
            ffma2(p11, wb.x, vb.x); ffma2(p11, wb.y, vb.y);
        }
        gsm[r0*33 + b0] = sum2(p00) + x00;
        gsm[r0*33 + b1] = sum2(p01) + x01;
        gsm[r1*33 + b0] = sum2(p10) + x10;
        gsm[r1*33 + b1] = sum2(p11) + x11;
        __syncthreads();

        // phase C
        {
            float iv = gsm[(cu*4 + 0)*33 + cb];
            float fv = gsm[(cu*4 + 1)*33 + cb];
            float gv = gsm[(cu*4 + 2)*33 + cb];
            float ov = gsm[(cu*4 + 3)*33 + cb];
            iv = 1.f / (1.f + __expf(-iv));
            fv = 1.f / (1.f + __expf(-fv));
            ov = 1.f / (1.f + __expf(-ov));
            gv = tanhf(gv);
            c_reg = fv * c_reg + iv * gv;
            float hn = ov * tanhf(c_reg);
            int nidx = n0 + cu;
            __stcg(&g_hping[(t + 1) & 1][cb * HID + nidx], hn);
            g_h_f16[((size_t)t * BATCH + cb) * HID + nidx] = __float2half_rn(hn);
        }
        if (t + 1 < TT) grid_barrier((unsigned)((t + 1) * NBLK_LSTM));
    }
}

// ---------------------------------------------------------------------------
// Tensor-core vocab GEMM, single fp16 product:  D = A(h) * B(Wv)
// 512 threads / 16 warps, warp tile 32x64; CTA tile 128x256, K-chunk 64,
// stage 48KB (A 16K | B 32K), 2 stages, cp.async pipeline.
// ---------------------------------------------------------------------------
#define VG_STAGE 49152

__global__ __launch_bounds__(512)
void gemm_vocab_mma_kernel(const float* __restrict__ bv, float* __restrict__ out)
{
    extern __shared__ char vsm[];
    const uint32_t smem = smem_u32(vsm);

    const int tid  = threadIdx.x;
    const int wid  = tid >> 5;
    const int lane = tid & 31;
    const int wm   = wid >> 2;          // 0..3  (32-row slabs)
    const int wn   = wid & 3;           // 0..3  (64-col slabs)
    const int n0   = blockIdx.x * 256;
    const int m0   = blockIdx.y * 128;

    float acc[2][8][4];
    #pragma unroll
    for (int i = 0; i < 2; i++)
        #pragma unroll
        for (int j = 0; j < 8; j++)
            #pragma unroll
            for (int q = 0; q < 4; q++) acc[i][j][q] = 0.f;

    // loader: 6 cp.async of 16B per thread per chunk (3072 total)
    auto load_chunk = [&](int chunk) {
        const uint32_t stage = smem + (uint32_t)(chunk & 1) * VG_STAGE;
        const int kbase = chunk * 64;
        #pragma unroll
        for (int j = 0; j < 6; j++) {
            int i = tid + j * 512;          // 0..3071
            const __half* gb;
            int grow;
            uint32_t doff;
            int cc;
            if (i < 1024) {                  // A: 128 rows x 8 chunks
                int r  = (i >> 3) & 127;
                cc = i & 7;
                gb = g_h_f16;
                grow = m0 + r;
                doff = (uint32_t)(r * 128) + (uint32_t)(((cc ^ (r & 7)) * 16));
            } else {                         // B: 256 rows x 8 chunks
                int jj = i - 1024;
                int r  = (jj >> 3) & 255;
                cc = jj & 7;
                gb = g_wv_f16;
                grow = n0 + r;
                doff = 16384u + (uint32_t)(r * 128) + (uint32_t)(((cc ^ (r & 7)) * 16));
            }
            cp_async16(stage + doff, gb + (size_t)grow * HID + kbase + cc * 8);
        }
        CP_ASYNC_COMMIT();
    };

    load_chunk(0);

    for (int chunk = 0; chunk < 8; chunk++) {
        if (chunk + 1 < 8) { load_chunk(chunk + 1); CP_ASYNC_WAIT(1); }
        else               { CP_ASYNC_WAIT(0); }
        __syncthreads();

        const uint32_t stage = smem + (uint32_t)(chunk & 1) * VG_STAGE;
        const uint32_t aBase = stage;               // A
        const uint32_t bBase = stage + 16384u;      // B

        #pragma unroll
        for (int ks = 0; ks < 4; ks++) {
            // A fragments: 2 m-tiles
            uint32_t ah[2][4];
            #pragma unroll
            for (int mt = 0; mt < 2; mt++) {
                int row = wm * 32 + mt * 16 + (lane & 7) + ((lane >> 3) & 1) * 8;
                int ch  = ks * 2 + (lane >> 4);
                uint32_t off = (uint32_t)(row * 128) + (uint32_t)((ch ^ (row & 7)) * 16);
                ldsm_x4(ah[mt][0], ah[mt][1], ah[mt][2], ah[mt][3], aBase + off);
            }
            // B: 4 groups of 16 cols
            #pragma unroll
            for (int p = 0; p < 4; p++) {
                int g   = lane >> 3;
                int row = wn * 64 + p * 16 + (g & 1) * 8 + (lane & 7);
                int ch  = ks * 2 + (g >> 1);
                uint32_t off = (uint32_t)(row * 128) + (uint32_t)((ch ^ (row & 7)) * 16);
                uint32_t bh[2][2];
                {
                    uint32_t r0, r1, r2, r3;
                    ldsm_x4(r0, r1, r2, r3, bBase + off);
                    bh[0][0] = r0; bh[0][1] = r2;
                    bh[1][0] = r1; bh[1][1] = r3;
                }
                #pragma unroll
                for (int mt = 0; mt < 2; mt++) {
                    #pragma unroll
                    for (int q = 0; q < 2; q++) {
                        int nt = p * 2 + q;
                        mma_f16(acc[mt][nt], ah[mt][0], ah[mt][1], ah[mt][2], ah[mt][3],
                                bh[q][0], bh[q][1]);
                    }
                }
            }
        }
        __syncthreads();
    }

    // epilogue: permuted rows, +bias, float2 stores
    #pragma unroll
    for (int mt = 0; mt < 2; mt++) {
        int gm0 = m0 + wm * 32 + mt * 16 + (lane >> 2);
        int gm1 = gm0 + 8;
        size_t ob0 = ((size_t)(gm0 & 31) * TT + (size_t)(gm0 >> 5)) * (size_t)VOCAB;
        size_t ob1 = ((size_t)(gm1 & 31) * TT + (size_t)(gm1 >> 5)) * (size_t)VOCAB;
        #pragma unroll
        for (int nt = 0; nt < 8; nt++) {
            int gn = n0 + wn * 64 + nt * 8 + (lane & 3) * 2;
            float bv0 = __ldg(bv + gn), bv1 = __ldg(bv + gn + 1);
            float2 v0 = make_float2(acc[mt][nt][0] + bv0, acc[mt][nt][1] + bv1);
            float2 v1 = make_float2(acc[mt][nt][2] + bv0, acc[mt][nt][3] + bv1);
            *reinterpret_cast<float2*>(out + ob0 + gn) = v0;
            *reinterpret_cast<float2*>(out + ob1 + gn) = v1;
        }
    }
}

// ---------------------------------------------------------------------------
// launch
// ---------------------------------------------------------------------------
extern "C" void kernel_launch(void* const* d_in, const int* in_sizes, int n_in,
                              void* d_out, int out_size) {
    const float* features  = (const float*)d_in[0];
    const int*   reports   = (const int*)  d_in[1];
    const float* emb_table = (const float*)d_in[2];
    const float* fc_w      = (const float*)d_in[3];
    const float* fc_b      = (const float*)d_in[4];
    const float* W_ih      = (const float*)d_in[5];
    const float* b_ih      = (const float*)d_in[6];
    const float* W_hh      = (const float*)d_in[7];
    const float* b_hh      = (const float*)d_in[8];
    const float* Wv        = (const float*)d_in[9];
    const float* bv        = (const float*)d_in[10];
    float* out = (float*)d_out;

    void *p_xg = nullptr, *p_tok = nullptr, *p_wv16 = nullptr;
    cudaGetSymbolAddress(&p_xg,   g_xg);
    cudaGetSymbolAddress(&p_tok,  g_tok);
    cudaGetSymbolAddress(&p_wv16, g_wv_f16);

    const int lstm_smem = (16*WS_STRIDE + 32*WS_STRIDE + 16*33) * (int)sizeof(float);
    cudaFuncSetAttribute(lstm_kernel, cudaFuncAttributeMaxDynamicSharedMemorySize, lstm_smem);
    const int vg_smem = 2 * VG_STAGE;   // 96 KB
    cudaFuncSetAttribute(gemm_vocab_mma_kernel, cudaFuncAttributeMaxDynamicSharedMemorySize, vg_smem);

    prep_kernel<<<(M_ROWS + 255) / 256, 256>>>(reports);
    pool_kernel<<<(BATCH * FEAT + 255) / 256, 256>>>(features);
    h0_kernel<<<(BATCH * HID + 255) / 256, 256>>>(fc_w, fc_b);
    {
        int n4 = VOCAB * HID / 4;
        cvt_wv_kernel<<<(n4 + 255) / 256, 256>>>(Wv, (__half*)p_wv16, n4);
    }
    gemm_gates_kernel<<<dim3(4*HID/128, M_ROWS/128), 256>>>(
        emb_table, W_ih, b_ih, b_hh, (float*)p_xg, 4*HID, EMB, (const int*)p_tok);
    lstm_kernel<<<NBLK_LSTM, 128, lstm_smem>>>(W_hh);
    gemm_vocab_mma_kernel<<<dim3(VOCAB/256, M_ROWS/128), 512, vg_smem>>>(bv, out);
}

// round 9
// speedup vs baseline: 2.7531x; 1.1392x over previous
#include <cuda_runtime.h>
#include <cuda_fp16.h>
#include <cstdint>
#include <cstddef>

#define VOCAB 32000
#define EMB   256
#define HID   512
#define FEAT  1024
#define BATCH 32
#define TT    100
#define M_ROWS (TT*BATCH)      // 3200
#define NBLK_LSTM 128
typedef unsigned long long ull;

// ---------------------------------------------------------------------------
// device scratch
// ---------------------------------------------------------------------------
__device__ float g_pooled[BATCH*FEAT];
__device__ float g_xg[(size_t)M_ROWS * 4 * HID];
__device__ float g_hping[2][BATCH*HID];
__device__ int   g_tok[M_ROWS];
__device__ unsigned g_barrier;

__device__ __half g_wv_f16[(size_t)VOCAB * HID];   // fp16 weights
__device__ __half g_h_f16[(size_t)M_ROWS * HID];   // fp16 h (written by LSTM role)

// ---------------------------------------------------------------------------
// helpers
// ---------------------------------------------------------------------------
__device__ __forceinline__ uint32_t smem_u32(const void* p) {
    uint32_t a;
    asm("{ .reg .u64 t; cvta.to.shared.u64 t, %1; cvt.u32.u64 %0, t; }" : "=r"(a) : "l"(p));
    return a;
}
__device__ __forceinline__ void cp_async16(uint32_t dst, const void* src) {
    asm volatile("cp.async.cg.shared.global [%0], [%1], 16;" :: "r"(dst), "l"(src) : "memory");
}
#define CP_ASYNC_COMMIT() asm volatile("cp.async.commit_group;" ::: "memory")
#define CP_ASYNC_WAIT(n)  asm volatile("cp.async.wait_group %0;" :: "n"(n) : "memory")

#define BAR_VOCAB() asm volatile("bar.sync 1, 512;" ::: "memory")
#define BAR_LSTM()  asm volatile("bar.sync 2, 128;" ::: "memory")

__device__ __forceinline__ void ldsm_x4(uint32_t& r0, uint32_t& r1, uint32_t& r2, uint32_t& r3,
                                        uint32_t addr) {
    asm volatile("ldmatrix.sync.aligned.m8n8.x4.shared.b16 {%0,%1,%2,%3}, [%4];"
                 : "=r"(r0), "=r"(r1), "=r"(r2), "=r"(r3) : "r"(addr));
}
__device__ __forceinline__ void mma_f16(float* c, uint32_t a0, uint32_t a1, uint32_t a2, uint32_t a3,
                                        uint32_t b0, uint32_t b1) {
    asm volatile("mma.sync.aligned.m16n8k16.row.col.f32.f16.f16.f32 "
                 "{%0,%1,%2,%3}, {%4,%5,%6,%7}, {%8,%9}, {%0,%1,%2,%3};"
                 : "+f"(c[0]), "+f"(c[1]), "+f"(c[2]), "+f"(c[3])
                 : "r"(a0), "r"(a1), "r"(a2), "r"(a3), "r"(b0), "r"(b1));
}

__device__ __forceinline__ ull pack2(float x, float y) {
    ull r;
    asm("mov.b64 %0, {%1, %2};" : "=l"(r) : "r"(__float_as_uint(x)), "r"(__float_as_uint(y)));
    return r;
}
__device__ __forceinline__ void ffma2(ull& d, ull a, ull b) {
    asm("fma.rn.f32x2 %0, %1, %2, %3;" : "=l"(d) : "l"(a), "l"(b), "l"(d));
}
__device__ __forceinline__ float sum2(ull p) {
    return __uint_as_float((unsigned)p) + __uint_as_float((unsigned)(p >> 32));
}

// ---------------------------------------------------------------------------
// prep / pool / h0 / weight convert
// ---------------------------------------------------------------------------
__global__ void prep_kernel(const int* __restrict__ reports) {
    int i = blockIdx.x * blockDim.x + threadIdx.x;
    if (i == 0) g_barrier = 0u;
    if (i < M_ROWS) {
        int t = i >> 5, b = i & 31;
        g_tok[i] = (t == 0) ? 1 : reports[b * TT + (t - 1)];
    }
}

__global__ void pool_kernel(const float* __restrict__ feat) {
    int i = blockIdx.x * blockDim.x + threadIdx.x;
    if (i < BATCH * FEAT) {
        const float* p = feat + (size_t)i * 49;
        float s = 0.f;
        #pragma unroll
        for (int j = 0; j < 49; j++) s += p[j];
        g_pooled[i] = s * (1.f / 49.f);
    }
}

__global__ void h0_kernel(const float* __restrict__ fc_w, const float* __restrict__ fc_b) {
    int i = blockIdx.x * blockDim.x + threadIdx.x;
    if (i >= BATCH * HID) return;
    int b = i >> 9, j = i & 511;
    const float* pw = fc_w + (size_t)j * FEAT;
    const float* pp = g_pooled + (size_t)b * FEAT;
    float acc = fc_b[j];
    #pragma unroll 4
    for (int k = 0; k < FEAT; k++) acc = fmaf(pw[k], pp[k], acc);
    g_hping[0][b * HID + j] = acc;
}

__global__ void cvt_wv_kernel(const float* __restrict__ src, __half* __restrict__ dst, int n4) {
    int i = blockIdx.x * blockDim.x + threadIdx.x;
    if (i >= n4) return;
    float4 v = reinterpret_cast<const float4*>(src)[i];
    reinterpret_cast<__half2*>(dst)[i*2]   = __halves2half2(__float2half_rn(v.x), __float2half_rn(v.y));
    reinterpret_cast<__half2*>(dst)[i*2+1] = __halves2half2(__float2half_rn(v.z), __float2half_rn(v.w));
}

// ---------------------------------------------------------------------------
// SIMT fp32 GEMM (gates)
// ---------------------------------------------------------------------------
__global__ __launch_bounds__(256)
void gemm_gates_kernel(const float* __restrict__ Asrc, const float* __restrict__ Bsrc,
                       const float* __restrict__ bias0, const float* __restrict__ bias1,
                       float* __restrict__ C, int N, int K, const int* __restrict__ gidx)
{
    __shared__ float As[16 * 132];
    __shared__ float Bs[16 * 132];
    const int tid = threadIdx.x;
    const int n0 = blockIdx.x * 128;
    const int m0 = blockIdx.y * 128;
    const int ty = tid >> 4;
    const int tx = tid & 15;

    ull acc[8][4];
    #pragma unroll
    for (int i = 0; i < 8; i++)
        #pragma unroll
        for (int j = 0; j < 4; j++) acc[i][j] = 0ull;

    const int ml = tid >> 2;
    const int kq = (tid & 3) * 4;
    const float* arow0 = Asrc + (size_t)gidx[m0 + ml] * K;
    const float* arow1 = Asrc + (size_t)gidx[m0 + ml + 64] * K;
    const float* brow0 = Bsrc + (size_t)(n0 + ml) * K;
    const float* brow1 = Bsrc + (size_t)(n0 + ml + 64) * K;

    for (int k0 = 0; k0 < K; k0 += 16) {
        float4 a0  = *reinterpret_cast<const float4*>(arow0 + k0 + kq);
        float4 a1  = *reinterpret_cast<const float4*>(arow1 + k0 + kq);
        float4 bb0 = *reinterpret_cast<const float4*>(brow0 + k0 + kq);
        float4 bb1 = *reinterpret_cast<const float4*>(brow1 + k0 + kq);
        __syncthreads();
        As[(kq+0)*132 + ml] = a0.x;  As[(kq+1)*132 + ml] = a0.y;
        As[(kq+2)*132 + ml] = a0.z;  As[(kq+3)*132 + ml] = a0.w;
        As[(kq+0)*132 + ml+64] = a1.x;  As[(kq+1)*132 + ml+64] = a1.y;
        As[(kq+2)*132 + ml+64] = a1.z;  As[(kq+3)*132 + ml+64] = a1.w;
        Bs[(kq+0)*132 + ml] = bb0.x; Bs[(kq+1)*132 + ml] = bb0.y;
        Bs[(kq+2)*132 + ml] = bb0.z; Bs[(kq+3)*132 + ml] = bb0.w;
        Bs[(kq+0)*132 + ml+64] = bb1.x; Bs[(kq+1)*132 + ml+64] = bb1.y;
        Bs[(kq+2)*132 + ml+64] = bb1.z; Bs[(kq+3)*132 + ml+64] = bb1.w;
        __syncthreads();

        #pragma unroll
        for (int kk = 0; kk < 16; kk++) {
            const float* ar = As + kk*132 + ty*8;
            const float* br = Bs + kk*132 + tx*8;
            float4 av0 = *reinterpret_cast<const float4*>(ar);
            float4 av1 = *reinterpret_cast<const float4*>(ar + 4);
            float4 bv0 = *reinterpret_cast<const float4*>(br);
            float4 bv1 = *reinterpret_cast<const float4*>(br + 4);
            ull bp0 = pack2(bv0.x, bv0.y);
            ull bp1 = pack2(bv0.z, bv0.w);
            ull bp2 = pack2(bv1.x, bv1.y);
            ull bp3 = pack2(bv1.z, bv1.w);
            float aa[8] = {av0.x, av0.y, av0.z, av0.w, av1.x, av1.y, av1.z, av1.w};
            #pragma unroll
            for (int i = 0; i < 8; i++) {
                ull ap = pack2(aa[i], aa[i]);
                ffma2(acc[i][0], ap, bp0);
                ffma2(acc[i][1], ap, bp1);
                ffma2(acc[i][2], ap, bp2);
                ffma2(acc[i][3], ap, bp3);
            }
        }
    }

    float bias[8];
    #pragma unroll
    for (int j = 0; j < 8; j++) {
        int n = n0 + tx*8 + j;
        bias[j] = bias0[n] + bias1[n];
    }
    #pragma unroll
    for (int i = 0; i < 8; i++) {
        int m = m0 + ty*8 + i;
        size_t base = (size_t)m * (size_t)N + (size_t)(n0 + tx*8);
        float o[8];
        #pragma unroll
        for (int j = 0; j < 4; j++) {
            o[2*j]   = __uint_as_float((unsigned)(acc[i][j]))       + bias[2*j];
            o[2*j+1] = __uint_as_float((unsigned)(acc[i][j] >> 32)) + bias[2*j+1];
        }
        *reinterpret_cast<float4*>(C + base)     = make_float4(o[0], o[1], o[2], o[3]);
        *reinterpret_cast<float4*>(C + base + 4) = make_float4(o[4], o[5], o[6], o[7]);
    }
}

// ---------------------------------------------------------------------------
// Fused LSTM + vocab GEMM mega-kernel.
// 3125 blocks x 640 threads, 1 block/SM (smem 195KB).
// threads 512..639 (warps 16-19, highest wid -> arbiter priority):
//   blocks 0..127 run the persistent LSTM (128 blocks, grid barrier on g_barrier)
// threads 0..511 (warps 0-15): vocab GEMM tile, spin-waits until its 4
//   timesteps of h are published (g_barrier >= (y*4+4)*128).
// smem: [0, LSTM_SMEM) lstm ws/hs/gsm | [LSTM_SMEM, +2*49152) vocab stages
// ---------------------------------------------------------------------------
#define WS_STRIDE 516
#define LSTM_SMEM_BYTES 101248          // 25296 floats = 101184, padded to 128B mult
#define VG_STAGE 49152
#define FUSED_SMEM (LSTM_SMEM_BYTES + 2*VG_STAGE)   // 199552

__device__ __forceinline__ void lstm_role(float* sm, const float* __restrict__ Whh, int ltid) {
    float* ws  = sm;
    float* hs  = sm + 16*WS_STRIDE;
    float* gsm = sm + 16*WS_STRIDE + 32*WS_STRIDE;

    const int n0 = blockIdx.x * 4;

    for (int lr = 0; lr < 16; lr++) {
        int u = lr >> 2, g = lr & 3;
        const float* src = Whh + (size_t)(g * HID + n0 + u) * HID;
        for (int k = ltid; k < HID; k += 128) ws[lr * WS_STRIDE + k] = src[k];
    }

    const int rp = (ltid & 1) + ((ltid >> 5) << 1);
    const int r0 = rp * 2, r1 = r0 + 1;
    const int bp = (ltid >> 1) & 15;
    const int b0 = bp * 2, b1 = b0 + 1;
    const int cu = ltid >> 5;
    const int cb = ltid & 31;
    const int g0 = (r0 & 3) * HID + n0 + (r0 >> 2);
    const int g1 = (r1 & 3) * HID + n0 + (r1 >> 2);
    float c_reg = 0.f;

    BAR_LSTM();

    for (int t = 0; t < TT; t++) {
        // xg prefetch
        const size_t xt = (size_t)t * BATCH * (4*HID);
        float x00 = __ldcg(&g_xg[xt + (size_t)b0 * (4*HID) + g0]);
        float x01 = __ldcg(&g_xg[xt + (size_t)b1 * (4*HID) + g0]);
        float x10 = __ldcg(&g_xg[xt + (size_t)b0 * (4*HID) + g1]);
        float x11 = __ldcg(&g_xg[xt + (size_t)b1 * (4*HID) + g1]);

        // phase A: h(ping) -> hs
        const float* hin = g_hping[t & 1];
        #pragma unroll 4
        for (int j = 0; j < 32; j++) {
            float4 v = __ldcg(reinterpret_cast<const float4*>(hin + j * HID + ltid * 4));
            *reinterpret_cast<float4*>(hs + j * WS_STRIDE + ltid * 4) = v;
        }
        BAR_LSTM();

        // phase B
        const ulonglong2* w0 = reinterpret_cast<const ulonglong2*>(ws + r0 * WS_STRIDE);
        const ulonglong2* w1 = reinterpret_cast<const ulonglong2*>(ws + r1 * WS_STRIDE);
        const ulonglong2* ha = reinterpret_cast<const ulonglong2*>(hs + b0 * WS_STRIDE);
        const ulonglong2* hb = reinterpret_cast<const ulonglong2*>(hs + b1 * WS_STRIDE);
        ull p00 = 0ull, p01 = 0ull, p10 = 0ull, p11 = 0ull;
        #pragma unroll 8
        for (int k = 0; k < HID/4; k++) {
            ulonglong2 wa = w0[k], wb = w1[k];
            ulonglong2 va = ha[k], vb = hb[k];
            ffma2(p00, wa.x, va.x); ffma2(p00, wa.y, va.y);
            ffma2(p01, wa.x, vb.x); ffma2(p01, wa.y, vb.y);
            ffma2(p10, wb.x, va.x); ffma2(p10, wb.y, va.y);
            ffma2(p11, wb.x, vb.x); ffma2(p11, wb.y, vb.y);
        }
        gsm[r0*33 + b0] = sum2(p00) + x00;
        gsm[r0*33 + b1] = sum2(p01) + x01;
        gsm[r1*33 + b0] = sum2(p10) + x10;
        gsm[r1*33 + b1] = sum2(p11) + x11;
        BAR_LSTM();

        // phase C
        {
            float iv = gsm[(cu*4 + 0)*33 + cb];
            float fv = gsm[(cu*4 + 1)*33 + cb];
            float gv = gsm[(cu*4 + 2)*33 + cb];
            float ov = gsm[(cu*4 + 3)*33 + cb];
            iv = 1.f / (1.f + __expf(-iv));
            fv = 1.f / (1.f + __expf(-fv));
            ov = 1.f / (1.f + __expf(-ov));
            gv = tanhf(gv);
            c_reg = fv * c_reg + iv * gv;
            float hn = ov * tanhf(c_reg);
            int nidx = n0 + cu;
            __stcg(&g_hping[(t + 1) & 1][cb * HID + nidx], hn);
            __stcg(reinterpret_cast<__half*>(&g_h_f16[((size_t)t * BATCH + cb) * HID + nidx]),
                   __float2half_rn(hn));
        }

        // publish: fence own writes, block-sync, then single arrive
        __threadfence();
        BAR_LSTM();
        if (ltid == 0) atomicAdd(&g_barrier, 1u);
        if (t + 1 < TT) {
            if (ltid == 0) {
                unsigned target = (unsigned)((t + 1) * NBLK_LSTM);
                while (*((volatile unsigned*)&g_barrier) < target) { __nanosleep(32); }
            }
            BAR_LSTM();
            __threadfence();
        }
    }
}

__device__ __forceinline__ void vocab_role(char* vsm_raw, const float* __restrict__ bv,
                                           float* __restrict__ out, int tid) {
    const uint32_t smem = smem_u32(vsm_raw);
    const int bid  = blockIdx.x;
    const int n0   = (bid % 125) * 256;
    const int yy   = bid / 125;
    const int m0   = yy * 128;
    const int wid  = tid >> 5;
    const int lane = tid & 31;
    const int wm   = wid >> 2;          // 0..3
    const int wn   = wid & 3;           // 0..3

    // wait until this tile's 4 timesteps of h are published
    if (tid == 0) {
        unsigned need = (unsigned)((yy * 4 + 4) * NBLK_LSTM);
        while (*((volatile unsigned*)&g_barrier) < need) { __nanosleep(256); }
    }
    BAR_VOCAB();
    __threadfence();

    float acc[2][8][4];
    #pragma unroll
    for (int i = 0; i < 2; i++)
        #pragma unroll
        for (int j = 0; j < 8; j++)
            #pragma unroll
            for (int q = 0; q < 4; q++) acc[i][j][q] = 0.f;

    auto load_chunk = [&](int chunk) {
        const uint32_t stage = smem + (uint32_t)(chunk & 1) * VG_STAGE;
        const int kbase = chunk * 64;
        #pragma unroll
        for (int j = 0; j < 6; j++) {
            int i = tid + j * 512;          // 0..3071
            const __half* gb;
            int grow;
            uint32_t doff;
            int cc;
            if (i < 1024) {                  // A: 128 rows x 8 chunks
                int r  = (i >> 3) & 127;
                cc = i & 7;
                gb = g_h_f16;
                grow = m0 + r;
                doff = (uint32_t)(r * 128) + (uint32_t)(((cc ^ (r & 7)) * 16));
            } else {                         // B: 256 rows x 8 chunks
                int jj = i - 1024;
                int r  = (jj >> 3) & 255;
                cc = jj & 7;
                gb = g_wv_f16;
                grow = n0 + r;
                doff = 16384u + (uint32_t)(r * 128) + (uint32_t)(((cc ^ (r & 7)) * 16));
            }
            cp_async16(stage + doff, gb + (size_t)grow * HID + kbase + cc * 8);
        }
        CP_ASYNC_COMMIT();
    };

    load_chunk(0);

    for (int chunk = 0; chunk < 8; chunk++) {
        if (chunk + 1 < 8) { load_chunk(chunk + 1); CP_ASYNC_WAIT(1); }
        else               { CP_ASYNC_WAIT(0); }
        BAR_VOCAB();

        const uint32_t stage = smem + (uint32_t)(chunk & 1) * VG_STAGE;
        const uint32_t aBase = stage;
        const uint32_t bBase = stage + 16384u;

        #pragma unroll
        for (int ks = 0; ks < 4; ks++) {
            uint32_t ah[2][4];
            #pragma unroll
            for (int mt = 0; mt < 2; mt++) {
                int row = wm * 32 + mt * 16 + (lane & 7) + ((lane >> 3) & 1) * 8;
                int ch  = ks * 2 + (lane >> 4);
                uint32_t off = (uint32_t)(row * 128) + (uint32_t)((ch ^ (row & 7)) * 16);
                ldsm_x4(ah[mt][0], ah[mt][1], ah[mt][2], ah[mt][3], aBase + off);
            }
            #pragma unroll
            for (int p = 0; p < 4; p++) {
                int g   = lane >> 3;
                int row = wn * 64 + p * 16 + (g & 1) * 8 + (lane & 7);
                int ch  = ks * 2 + (g >> 1);
                uint32_t off = (uint32_t)(row * 128) + (uint32_t)((ch ^ (row & 7)) * 16);
                uint32_t bh[2][2];
                {
                    uint32_t r0, r1, r2, r3;
                    ldsm_x4(r0, r1, r2, r3, bBase + off);
                    bh[0][0] = r0; bh[0][1] = r2;
                    bh[1][0] = r1; bh[1][1] = r3;
                }
                #pragma unroll
                for (int mt = 0; mt < 2; mt++) {
                    #pragma unroll
                    for (int q = 0; q < 2; q++) {
                        int nt = p * 2 + q;
                        mma_f16(acc[mt][nt], ah[mt][0], ah[mt][1], ah[mt][2], ah[mt][3],
                                bh[q][0], bh[q][1]);
                    }
                }
            }
        }
        BAR_VOCAB();
    }

    // epilogue: permuted rows, +bias, float2 stores
    #pragma unroll
    for (int mt = 0; mt < 2; mt++) {
        int gm0 = m0 + wm * 32 + mt * 16 + (lane >> 2);
        int gm1 = gm0 + 8;
        size_t ob0 = ((size_t)(gm0 & 31) * TT + (size_t)(gm0 >> 5)) * (size_t)VOCAB;
        size_t ob1 = ((size_t)(gm1 & 31) * TT + (size_t)(gm1 >> 5)) * (size_t)VOCAB;
        #pragma unroll
        for (int nt = 0; nt < 8; nt++) {
            int gn = n0 + wn * 64 + nt * 8 + (lane & 3) * 2;
            float bv0 = __ldg(bv + gn), bv1 = __ldg(bv + gn + 1);
            float2 v0 = make_float2(acc[mt][nt][0] + bv0, acc[mt][nt][1] + bv1);
            float2 v1 = make_float2(acc[mt][nt][2] + bv0, acc[mt][nt][3] + bv1);
            *reinterpret_cast<float2*>(out + ob0 + gn) = v0;
            *reinterpret_cast<float2*>(out + ob1 + gn) = v1;
        }
    }
}

__global__ __launch_bounds__(640, 1)
void fused_kernel(const float* __restrict__ Whh, const float* __restrict__ bv,
                  float* __restrict__ out)
{
    extern __shared__ char sm_raw[];
    const int tid = threadIdx.x;
    if (tid >= 512) {
        if (blockIdx.x < NBLK_LSTM)
            lstm_role(reinterpret_cast<float*>(sm_raw), Whh, tid - 512);
        return;
    }
    vocab_role(sm_raw + LSTM_SMEM_BYTES, bv, out, tid);
}

// ---------------------------------------------------------------------------
// launch
// ---------------------------------------------------------------------------
extern "C" void kernel_launch(void* const* d_in, const int* in_sizes, int n_in,
                              void* d_out, int out_size) {
    const float* features  = (const float*)d_in[0];
    const int*   reports   = (const int*)  d_in[1];
    const float* emb_table = (const float*)d_in[2];
    const float* fc_w      = (const float*)d_in[3];
    const float* fc_b      = (const float*)d_in[4];
    const float* W_ih      = (const float*)d_in[5];
    const float* b_ih      = (const float*)d_in[6];
    const float* W_hh      = (const float*)d_in[7];
    const float* b_hh      = (const float*)d_in[8];
    const float* Wv        = (const float*)d_in[9];
    const float* bv        = (const float*)d_in[10];
    float* out = (float*)d_out;

    void *p_xg = nullptr, *p_tok = nullptr, *p_wv16 = nullptr;
    cudaGetSymbolAddress(&p_xg,   g_xg);
    cudaGetSymbolAddress(&p_tok,  g_tok);
    cudaGetSymbolAddress(&p_wv16, g_wv_f16);

    cudaFuncSetAttribute(fused_kernel, cudaFuncAttributeMaxDynamicSharedMemorySize, FUSED_SMEM);

    prep_kernel<<<(M_ROWS + 255) / 256, 256>>>(reports);
    pool_kernel<<<(BATCH * FEAT + 255) / 256, 256>>>(features);
    h0_kernel<<<(BATCH * HID + 255) / 256, 256>>>(fc_w, fc_b);
    {
        int n4 = VOCAB * HID / 4;
        cvt_wv_kernel<<<(n4 + 255) / 256, 256>>>(Wv, (__half*)p_wv16, n4);
    }
    gemm_gates_kernel<<<dim3(4*HID/128, M_ROWS/128), 256>>>(
        emb_table, W_ih, b_ih, b_hh, (float*)p_xg, 4*HID, EMB, (const int*)p_tok);
    // fused LSTM (blocks 0..127, warps 16-19) + vocab GEMM (all blocks, warps 0-15)
    fused_kernel<<<125 * 25, 640, FUSED_SMEM>>>(W_hh, bv, out);
}